// round 1
// baseline (speedup 1.0000x reference)
#include <cuda_runtime.h>
#include <math.h>

#define NTOK 8192
#define DD   512
#define FFD  2048
#define GG   102
#define GAM  0.5f
#define NEGV (-1e9f)
#define QKSCALE 0.044194173824159216f   // 1/sqrt(512)

// ---------------- scratch (device globals: no allocation allowed) ----------
static __device__ float g_dropx[NTOK * DD];
static __device__ float g_q [NTOK * DD];
static __device__ float g_k [NTOK * DD];
static __device__ float g_qf[NTOK * DD];
static __device__ float g_kf[NTOK * DD];
static __device__ float g_v [NTOK * DD];
static __device__ float g_t0[NTOK * DD];
static __device__ float g_h1[NTOK * DD];
static __device__ float g_h2[NTOK * DD];
static __device__ float g_ffb[NTOK * FFD];
static __device__ float g_Sr[(size_t)NTOK * NTOK];   // 256 MB
static __device__ float g_Sf[(size_t)NTOK * NTOK];   // 256 MB
static __device__ float g_rinv[NTOK];

// ---------------- drop_x build + x_init gather ------------------------------
__global__ void k_drop(const float* __restrict__ x, const int* __restrict__ idx,
                       float* __restrict__ dx, float* __restrict__ out_init) {
    int r = blockIdx.x;
    const float* xr = x + (size_t)r * DD;
    float* dr = dx + (size_t)r * DD;
    for (int c = threadIdx.x; c < DD; c += blockDim.x) dr[c] = xr[c];
    __syncthreads();
    for (int g = threadIdx.x; g < GG; g += blockDim.x) {
        int c = idx[r * GG + g];
        out_init[r * GG + g] = xr[c];
        dr[c] = 0.0f;
    }
}

// ---------------- generic SGEMM (NN): C = A[MxK] @ B[KxNc] ------------------
// EPI: 0 plain, 1 +bias, 2 +bias then exact GELU, 3 per-row scale (rs[m])
// All dims assumed multiples of tile sizes (true for this problem).
template <int EPI>
__global__ __launch_bounds__(256) void k_gemm_nn(
    const float* __restrict__ A, const float* __restrict__ B, float* __restrict__ C,
    int M, int Nc, int K,
    const float* __restrict__ bias, const float* __restrict__ rs)
{
    __shared__ float As[16][128];
    __shared__ float Bs[16][128];
    int tid = threadIdx.x;
    int bx = blockIdx.x, by = blockIdx.y;
    int tx = tid & 15, ty = tid >> 4;
    const int arow = tid >> 2;          // 0..63
    const int acol = (tid & 3) << 2;    // 0,4,8,12
    const int brow = tid >> 5;          // 0..7
    const int bcol = (tid & 31) << 2;   // 0..124

    float acc[8][8];
#pragma unroll
    for (int i = 0; i < 8; i++)
#pragma unroll
        for (int j = 0; j < 8; j++) acc[i][j] = 0.0f;

    const size_t Abase = (size_t)by * 128 * K;
    const size_t Bbase = (size_t)bx * 128;

    for (int k0 = 0; k0 < K; k0 += 16) {
        float4 a0 = *(const float4*)&A[Abase + (size_t)arow        * K + k0 + acol];
        float4 a1 = *(const float4*)&A[Abase + (size_t)(arow + 64) * K + k0 + acol];
        float4 b0 = *(const float4*)&B[(size_t)(k0 + brow)     * Nc + Bbase + bcol];
        float4 b1 = *(const float4*)&B[(size_t)(k0 + brow + 8) * Nc + Bbase + bcol];
        __syncthreads();
        As[acol + 0][arow] = a0.x; As[acol + 1][arow] = a0.y;
        As[acol + 2][arow] = a0.z; As[acol + 3][arow] = a0.w;
        As[acol + 0][arow + 64] = a1.x; As[acol + 1][arow + 64] = a1.y;
        As[acol + 2][arow + 64] = a1.z; As[acol + 3][arow + 64] = a1.w;
        *(float4*)&Bs[brow][bcol]     = b0;
        *(float4*)&Bs[brow + 8][bcol] = b1;
        __syncthreads();
#pragma unroll
        for (int kk = 0; kk < 16; kk++) {
            float ar[8], br[8]; float4 t;
            t = *(const float4*)&As[kk][ty * 8];     ar[0]=t.x; ar[1]=t.y; ar[2]=t.z; ar[3]=t.w;
            t = *(const float4*)&As[kk][ty * 8 + 4]; ar[4]=t.x; ar[5]=t.y; ar[6]=t.z; ar[7]=t.w;
            t = *(const float4*)&Bs[kk][tx * 8];     br[0]=t.x; br[1]=t.y; br[2]=t.z; br[3]=t.w;
            t = *(const float4*)&Bs[kk][tx * 8 + 4]; br[4]=t.x; br[5]=t.y; br[6]=t.z; br[7]=t.w;
#pragma unroll
            for (int i = 0; i < 8; i++)
#pragma unroll
                for (int j = 0; j < 8; j++) acc[i][j] += ar[i] * br[j];
        }
    }

#pragma unroll
    for (int i = 0; i < 8; i++) {
        int m = by * 128 + ty * 8 + i;
        float rsv = 1.0f;
        if (EPI == 3) rsv = rs[m];
#pragma unroll
        for (int jj = 0; jj < 2; jj++) {
            int n0 = bx * 128 + tx * 8 + jj * 4;
            float vv[4];
#pragma unroll
            for (int q = 0; q < 4; q++) {
                float v = acc[i][jj * 4 + q];
                if (EPI == 1 || EPI == 2) v += bias[n0 + q];
                if (EPI == 2) v = 0.5f * v * (1.0f + erff(v * 0.7071067811865475f));
                if (EPI == 3) v *= rsv;
                vv[q] = v;
            }
            float4 o; o.x = vv[0]; o.y = vv[1]; o.z = vv[2]; o.w = vv[3];
            *(float4*)&C[(size_t)m * Nc + n0] = o;
        }
    }
}

// ------------- score SGEMM (NT): S = mask? NEG : (Q @ Kt^T)*scale ----------
// Q: [NTOK x K], Kt: [NTOK x K] (both K-contiguous). mask word nonzero = masked.
__global__ __launch_bounds__(256) void k_gemm_nt_score(
    const float* __restrict__ Qm, const float* __restrict__ Km,
    const int* __restrict__ mask, float* __restrict__ S, int K)
{
    __shared__ float As[16][128];
    __shared__ float Bs[16][128];
    int tid = threadIdx.x;
    int bx = blockIdx.x, by = blockIdx.y;
    int tx = tid & 15, ty = tid >> 4;
    const int arow = tid >> 2;
    const int acol = (tid & 3) << 2;

    float acc[8][8];
#pragma unroll
    for (int i = 0; i < 8; i++)
#pragma unroll
        for (int j = 0; j < 8; j++) acc[i][j] = 0.0f;

    const size_t Abase = (size_t)by * 128 * K;
    const size_t Bbase = (size_t)bx * 128 * K;

    for (int k0 = 0; k0 < K; k0 += 16) {
        float4 a0 = *(const float4*)&Qm[Abase + (size_t)arow        * K + k0 + acol];
        float4 a1 = *(const float4*)&Qm[Abase + (size_t)(arow + 64) * K + k0 + acol];
        float4 b0 = *(const float4*)&Km[Bbase + (size_t)arow        * K + k0 + acol];
        float4 b1 = *(const float4*)&Km[Bbase + (size_t)(arow + 64) * K + k0 + acol];
        __syncthreads();
        As[acol + 0][arow] = a0.x; As[acol + 1][arow] = a0.y;
        As[acol + 2][arow] = a0.z; As[acol + 3][arow] = a0.w;
        As[acol + 0][arow + 64] = a1.x; As[acol + 1][arow + 64] = a1.y;
        As[acol + 2][arow + 64] = a1.z; As[acol + 3][arow + 64] = a1.w;
        Bs[acol + 0][arow] = b0.x; Bs[acol + 1][arow] = b0.y;
        Bs[acol + 2][arow] = b0.z; Bs[acol + 3][arow] = b0.w;
        Bs[acol + 0][arow + 64] = b1.x; Bs[acol + 1][arow + 64] = b1.y;
        Bs[acol + 2][arow + 64] = b1.z; Bs[acol + 3][arow + 64] = b1.w;
        __syncthreads();
#pragma unroll
        for (int kk = 0; kk < 16; kk++) {
            float ar[8], br[8]; float4 t;
            t = *(const float4*)&As[kk][ty * 8];     ar[0]=t.x; ar[1]=t.y; ar[2]=t.z; ar[3]=t.w;
            t = *(const float4*)&As[kk][ty * 8 + 4]; ar[4]=t.x; ar[5]=t.y; ar[6]=t.z; ar[7]=t.w;
            t = *(const float4*)&Bs[kk][tx * 8];     br[0]=t.x; br[1]=t.y; br[2]=t.z; br[3]=t.w;
            t = *(const float4*)&Bs[kk][tx * 8 + 4]; br[4]=t.x; br[5]=t.y; br[6]=t.z; br[7]=t.w;
#pragma unroll
            for (int i = 0; i < 8; i++)
#pragma unroll
                for (int j = 0; j < 8; j++) acc[i][j] += ar[i] * br[j];
        }
    }

#pragma unroll
    for (int i = 0; i < 8; i++) {
        size_t m = (size_t)(by * 128 + ty * 8 + i);
        const int* mr = mask + m * NTOK + bx * 128 + tx * 8;
#pragma unroll
        for (int jj = 0; jj < 2; jj++) {
            int4 mk = *(const int4*)&mr[jj * 4];
            float4 o;
            o.x = mk.x ? NEGV : acc[i][jj * 4 + 0] * QKSCALE;
            o.y = mk.y ? NEGV : acc[i][jj * 4 + 1] * QKSCALE;
            o.z = mk.z ? NEGV : acc[i][jj * 4 + 2] * QKSCALE;
            o.w = mk.w ? NEGV : acc[i][jj * 4 + 3] * QKSCALE;
            *(float4*)&S[m * NTOK + bx * 128 + tx * 8 + jj * 4] = o;
        }
    }
}

// ------------- dual softmax combine: P=exp(sr-m)+g*exp(sf-m), rinv=1/sum ---
__global__ void k_softmax(float* __restrict__ Sr, const float* __restrict__ Sf,
                          float* __restrict__ rinv) {
    int r = blockIdx.x, tid = threadIdx.x;
    float* sr = Sr + (size_t)r * NTOK;
    const float* sf = Sf + (size_t)r * NTOK;
    __shared__ float red[256];
    float m = -3.4e38f;
    for (int j = tid * 4; j < NTOK; j += 1024) {
        float4 a = *(const float4*)&sr[j];
        float4 b = *(const float4*)&sf[j];
        m = fmaxf(m, fmaxf(fmaxf(a.x, a.y), fmaxf(a.z, a.w)));
        m = fmaxf(m, fmaxf(fmaxf(b.x, b.y), fmaxf(b.z, b.w)));
    }
    red[tid] = m; __syncthreads();
    for (int s = 128; s > 0; s >>= 1) {
        if (tid < s) red[tid] = fmaxf(red[tid], red[tid + s]);
        __syncthreads();
    }
    m = red[0]; __syncthreads();

    float sum = 0.0f;
    for (int j = tid * 4; j < NTOK; j += 1024) {
        float4 a = *(const float4*)&sr[j];
        float4 b = *(const float4*)&sf[j];
        float4 p;
        p.x = expf(a.x - m) + GAM * expf(b.x - m);
        p.y = expf(a.y - m) + GAM * expf(b.y - m);
        p.z = expf(a.z - m) + GAM * expf(b.z - m);
        p.w = expf(a.w - m) + GAM * expf(b.w - m);
        sum += p.x + p.y + p.z + p.w;
        *(float4*)&sr[j] = p;
    }
    red[tid] = sum; __syncthreads();
    for (int s = 128; s > 0; s >>= 1) {
        if (tid < s) red[tid] += red[tid + s];
        __syncthreads();
    }
    if (tid == 0) rinv[r] = 1.0f / red[0];
}

// ------------- residual add + LayerNorm (128 threads, 4 elems each) --------
__global__ void k_addln(const float* __restrict__ a, const float* __restrict__ b,
                        const float* __restrict__ g, const float* __restrict__ bb,
                        float* __restrict__ out) {
    int r = blockIdx.x, tid = threadIdx.x;
    __shared__ float s1[128], s2[128];
    const float* ar = a + (size_t)r * DD;
    const float* br = b + (size_t)r * DD;
    float4 va = *(const float4*)&ar[tid * 4];
    float4 vb = *(const float4*)&br[tid * 4];
    float v0 = va.x + vb.x, v1 = va.y + vb.y, v2 = va.z + vb.z, v3 = va.w + vb.w;
    s1[tid] = v0 + v1 + v2 + v3;
    s2[tid] = v0 * v0 + v1 * v1 + v2 * v2 + v3 * v3;
    __syncthreads();
    for (int s = 64; s > 0; s >>= 1) {
        if (tid < s) { s1[tid] += s1[tid + s]; s2[tid] += s2[tid + s]; }
        __syncthreads();
    }
    float mu = s1[0] * (1.0f / DD);
    float var = s2[0] * (1.0f / DD) - mu * mu;
    float rstd = rsqrtf(var + 1e-5f);
    int c = tid * 4;
    float4 o;
    o.x = (v0 - mu) * rstd * g[c + 0] + bb[c + 0];
    o.y = (v1 - mu) * rstd * g[c + 1] + bb[c + 1];
    o.z = (v2 - mu) * rstd * g[c + 2] + bb[c + 2];
    o.w = (v3 - mu) * rstd * g[c + 3] + bb[c + 3];
    *(float4*)&out[(size_t)r * DD + c] = o;
}

// ------------- final gather -------------------------------------------------
__global__ void k_gather(const float* __restrict__ H, const int* __restrict__ idx,
                         float* __restrict__ out) {
    int r = blockIdx.x;
    for (int g = threadIdx.x; g < GG; g += blockDim.x)
        out[r * GG + g] = H[(size_t)r * DD + idx[r * GG + g]];
}

// ------------- host side ----------------------------------------------------
static void run_attention(const float* h,
                          const float* Wqr, const float* Wkr,
                          const float* Wqf, const float* Wkf, const float* Wv,
                          const int* rmask, const int* fmask,
                          float* q, float* k, float* qf, float* kf, float* v,
                          float* Sr, float* Sf, float* rinv, float* outbuf) {
    dim3 g1(DD / 128, NTOK / 128);
    k_gemm_nn<0><<<g1, 256>>>(h, Wqr, q,  NTOK, DD, DD, nullptr, nullptr);
    k_gemm_nn<0><<<g1, 256>>>(h, Wkr, k,  NTOK, DD, DD, nullptr, nullptr);
    k_gemm_nn<0><<<g1, 256>>>(h, Wqf, qf, NTOK, DD, DD, nullptr, nullptr);
    k_gemm_nn<0><<<g1, 256>>>(h, Wkf, kf, NTOK, DD, DD, nullptr, nullptr);
    k_gemm_nn<0><<<g1, 256>>>(h, Wv,  v,  NTOK, DD, DD, nullptr, nullptr);
    dim3 gs(NTOK / 128, NTOK / 128);
    k_gemm_nt_score<<<gs, 256>>>(q,  k,  rmask, Sr, DD);
    k_gemm_nt_score<<<gs, 256>>>(qf, kf, fmask, Sf, DD);
    k_softmax<<<NTOK, 256>>>(Sr, Sf, rinv);
    k_gemm_nn<3><<<g1, 256>>>(Sr, v, outbuf, NTOK, DD, NTOK, nullptr, rinv);
}

extern "C" void kernel_launch(void* const* d_in, const int* in_sizes, int n_in,
                              void* d_out, int out_size) {
    const float* x    = (const float*)d_in[0];
    const int*   idx  = (const int*)  d_in[1];
    const int*   rmsk = (const int*)  d_in[2];   // nonzero word == True(masked)
    const int*   fmsk = (const int*)  d_in[3];
    const float* eWqr = (const float*)d_in[4];
    const float* eWkr = (const float*)d_in[5];
    const float* eWqf = (const float*)d_in[6];
    const float* eWkf = (const float*)d_in[7];
    const float* eWv  = (const float*)d_in[8];
    const float* dWqr = (const float*)d_in[9];
    const float* dWkr = (const float*)d_in[10];
    const float* dWqf = (const float*)d_in[11];
    const float* dWkf = (const float*)d_in[12];
    const float* dWv  = (const float*)d_in[13];
    const float* fW1  = (const float*)d_in[14];
    const float* fb1  = (const float*)d_in[15];
    const float* fW2  = (const float*)d_in[16];
    const float* fb2  = (const float*)d_in[17];
    const float* l1g  = (const float*)d_in[18];
    const float* l1b  = (const float*)d_in[19];
    const float* l2g  = (const float*)d_in[20];
    const float* l2b  = (const float*)d_in[21];
    const float* l3g  = (const float*)d_in[22];
    const float* l3b  = (const float*)d_in[23];
    const float* hW   = (const float*)d_in[24];
    const float* hb   = (const float*)d_in[25];

    float* out       = (float*)d_out;
    float* out_init  = out;                          // [N,G]
    float* out_recon = out + (size_t)NTOK * GG;      // [N,G]

    float *dropx, *q, *k, *qf, *kf, *v, *t0, *h1, *h2, *ffb, *Sr, *Sf, *rinv;
    cudaGetSymbolAddress((void**)&dropx, g_dropx);
    cudaGetSymbolAddress((void**)&q,  g_q);
    cudaGetSymbolAddress((void**)&k,  g_k);
    cudaGetSymbolAddress((void**)&qf, g_qf);
    cudaGetSymbolAddress((void**)&kf, g_kf);
    cudaGetSymbolAddress((void**)&v,  g_v);
    cudaGetSymbolAddress((void**)&t0, g_t0);
    cudaGetSymbolAddress((void**)&h1, g_h1);
    cudaGetSymbolAddress((void**)&h2, g_h2);
    cudaGetSymbolAddress((void**)&ffb, g_ffb);
    cudaGetSymbolAddress((void**)&Sr, g_Sr);
    cudaGetSymbolAddress((void**)&Sf, g_Sf);
    cudaGetSymbolAddress((void**)&rinv, g_rinv);

    // drop_x + x_init output
    k_drop<<<NTOK, 128>>>(x, idx, dropx, out_init);

    // encoder attention
    run_attention(dropx, eWqr, eWkr, eWqf, eWkf, eWv, rmsk, fmsk,
                  q, k, qf, kf, v, Sr, Sf, rinv, t0);
    k_addln<<<NTOK, 128>>>(t0, dropx, l1g, l1b, h1);

    // feed-forward
    dim3 gf1(FFD / 128, NTOK / 128);
    k_gemm_nn<2><<<gf1, 256>>>(h1, fW1, ffb, NTOK, FFD, DD, fb1, nullptr);
    dim3 gf2(DD / 128, NTOK / 128);
    k_gemm_nn<1><<<gf2, 256>>>(ffb, fW2, t0, NTOK, DD, FFD, fb2, nullptr);
    k_addln<<<NTOK, 128>>>(t0, h1, l2g, l2b, h2);

    // decoder attention
    run_attention(h2, dWqr, dWkr, dWqf, dWkf, dWv, rmsk, fmsk,
                  q, k, qf, kf, v, Sr, Sf, rinv, t0);
    k_addln<<<NTOK, 128>>>(t0, h2, l3g, l3b, h1);

    // head + x_recon gather
    dim3 gh(DD / 128, NTOK / 128);
    k_gemm_nn<1><<<gh, 256>>>(h1, hW, t0, NTOK, DD, DD, hb, nullptr);
    k_gather<<<NTOK, 128>>>(t0, idx, out_recon);
}

// round 3
// speedup vs baseline: 1.0439x; 1.0439x over previous
#include <cuda_runtime.h>
#include <math.h>
#include <stdint.h>

#define NTOK 8192
#define DD   512
#define FFD  2048
#define GG   102
#define GAM  0.5f
#define NEGV (-1e9f)
#define QKSCALE 0.044194173824159216f   // 1/sqrt(512)

// ================= scratch (device globals; no allocation allowed) =========
static __device__ float g_dropx[NTOK * DD];
static __device__ float g_q [NTOK * DD];
static __device__ float g_k [NTOK * DD];
static __device__ float g_qf[NTOK * DD];
static __device__ float g_kf[NTOK * DD];
static __device__ float g_v [NTOK * DD];
static __device__ float g_vt[NTOK * DD];          // V transposed [DD, NTOK]
static __device__ float g_t0[NTOK * DD];
static __device__ float g_h1[NTOK * DD];
static __device__ float g_h2[NTOK * DD];
static __device__ float g_ffb[NTOK * FFD];
static __device__ float g_Sr[(size_t)NTOK * NTOK];   // 256 MB
static __device__ float g_Sf[(size_t)NTOK * NTOK];   // 256 MB
static __device__ float g_rinv[NTOK];
static __device__ float g_wt[11 * DD * DD + DD * FFD + FFD * DD];

// ================= helpers =================================================
__device__ __forceinline__ uint32_t f2tf32(float f) {
    uint32_t u;
    asm("cvt.rna.tf32.f32 %0, %1;" : "=r"(u) : "f"(f));
    return u;
}

__device__ __forceinline__ void mma_tf32(float* d, uint32_t a0, uint32_t a1,
                                         uint32_t a2, uint32_t a3,
                                         uint32_t b0, uint32_t b1) {
    asm volatile(
        "mma.sync.aligned.m16n8k8.row.col.f32.tf32.tf32.f32 "
        "{%0,%1,%2,%3}, {%4,%5,%6,%7}, {%8,%9}, {%0,%1,%2,%3};"
        : "+f"(d[0]), "+f"(d[1]), "+f"(d[2]), "+f"(d[3])
        : "r"(a0), "r"(a1), "r"(a2), "r"(a3), "r"(b0), "r"(b1));
}

// ================ mma.sync tf32 NT GEMM: C[M,Nc] = A[M,K] @ B[Nc,K]^T =======
// CTA tile 128x128, 256 threads, 8 warps (2m x 4n), warp tile 64x32,
// K chunks of 16, double-buffered SMEM with k-permuted + swizzled layout.
// Permutation: word p(k) = (k%4)*4 + k/4, per-row XOR swizzle on 4-word groups.
// EPI: 0 plain, 1 +bias, 2 +bias+GELU, 3 row-scale rs[m], 4 score mask+QKSCALE
template <int EPI>
__global__ void __launch_bounds__(256, 1) k_mma_gemm(
    const float* __restrict__ A, const float* __restrict__ B, float* __restrict__ C,
    int M, int Nc, int K,
    const float* __restrict__ bias, const float* __restrict__ rs,
    const int* __restrict__ mask)
{
    __shared__ uint32_t As[2][128 * 16];
    __shared__ uint32_t Bs[2][128 * 16];

    const int tid = threadIdx.x;
    const int wid = tid >> 5;
    const int lane = tid & 31;
    const int wm = wid >> 2;          // 0..1
    const int wn = wid & 3;           // 0..3
    const int bx = blockIdx.x, by = blockIdx.y;

    // staging role: threads 0-127 stage A rows, 128-255 stage B rows
    const int half = tid >> 7;
    const int r = tid & 127;
    const float* src = half ? (B + (size_t)(bx * 128 + r) * K)
                            : (A + (size_t)(by * 128 + r) * K);
    const int rot = (r >> 1) & 3;
    const int rowbase = r * 16;

    float acc[4][4][4];
#pragma unroll
    for (int i = 0; i < 4; i++)
#pragma unroll
        for (int j = 0; j < 4; j++)
#pragma unroll
            for (int q = 0; q < 4; q++) acc[i][j][q] = 0.0f;

    const int nch = K >> 4;

    // ---- stage chunk 0 ----
    {
        float4 f[4];
#pragma unroll
        for (int q = 0; q < 4; q++) f[q] = *(const float4*)(src + q * 4);
        uint32_t u[16];
#pragma unroll
        for (int q = 0; q < 4; q++) {
            u[q * 4 + 0] = f2tf32(f[q].x); u[q * 4 + 1] = f2tf32(f[q].y);
            u[q * 4 + 2] = f2tf32(f[q].z); u[q * 4 + 3] = f2tf32(f[q].w);
        }
        uint32_t* dst = half ? &Bs[0][0] : &As[0][0];
#pragma unroll
        for (int g = 0; g < 4; g++) {
            uint4 pv = make_uint4(u[g], u[4 + g], u[8 + g], u[12 + g]);
            *(uint4*)&dst[rowbase + ((g ^ rot) << 2)] = pv;
        }
    }
    __syncthreads();

    for (int c = 0; c < nch; ++c) {
        const int s = c & 1;
        // prefetch next chunk to regs
        float4 f[4];
        if (c + 1 < nch) {
            const float* sp = src + (c + 1) * 16;
#pragma unroll
            for (int q = 0; q < 4; q++) f[q] = *(const float4*)(sp + q * 4);
        }

        // ---- load fragments ----
        uint4 fa[4][2];
#pragma unroll
        for (int mt = 0; mt < 4; mt++)
#pragma unroll
            for (int h = 0; h < 2; h++) {
                int rl = wm * 64 + mt * 16 + (lane >> 2) + h * 8;
                int g = (lane & 3) ^ ((rl >> 1) & 3);
                fa[mt][h] = *(const uint4*)&As[s][rl * 16 + (g << 2)];
            }
        uint4 fb[4];
#pragma unroll
        for (int nt = 0; nt < 4; nt++) {
            int nl = wn * 32 + nt * 8 + (lane >> 2);
            int g = (lane & 3) ^ ((nl >> 1) & 3);
            fb[nt] = *(const uint4*)&Bs[s][nl * 16 + (g << 2)];
        }

        // ---- 32 mma (2 k-steps x 4 mt x 4 nt) ----
#pragma unroll
        for (int mt = 0; mt < 4; mt++)
#pragma unroll
            for (int nt = 0; nt < 4; nt++) {
                mma_tf32(acc[mt][nt], fa[mt][0].x, fa[mt][1].x,
                         fa[mt][0].y, fa[mt][1].y, fb[nt].x, fb[nt].y);
                mma_tf32(acc[mt][nt], fa[mt][0].z, fa[mt][1].z,
                         fa[mt][0].w, fa[mt][1].w, fb[nt].z, fb[nt].w);
            }

        // ---- store next chunk into other buffer ----
        if (c + 1 < nch) {
            uint32_t u[16];
#pragma unroll
            for (int q = 0; q < 4; q++) {
                u[q * 4 + 0] = f2tf32(f[q].x); u[q * 4 + 1] = f2tf32(f[q].y);
                u[q * 4 + 2] = f2tf32(f[q].z); u[q * 4 + 3] = f2tf32(f[q].w);
            }
            uint32_t* dst = half ? &Bs[s ^ 1][0] : &As[s ^ 1][0];
#pragma unroll
            for (int g = 0; g < 4; g++) {
                uint4 pv = make_uint4(u[g], u[4 + g], u[8 + g], u[12 + g]);
                *(uint4*)&dst[rowbase + ((g ^ rot) << 2)] = pv;
            }
        }
        __syncthreads();
    }

    // ---- epilogue ----
    const int col_b = bx * 128 + wn * 32 + (lane & 3) * 2;
#pragma unroll
    for (int mt = 0; mt < 4; mt++) {
#pragma unroll
        for (int h = 0; h < 2; h++) {
            int row = by * 128 + wm * 64 + mt * 16 + (lane >> 2) + h * 8;
            float rsv = (EPI == 3) ? rs[row] : 1.0f;
            float* Cr = C + (size_t)row * Nc;
            const int* Mr = (EPI == 4) ? (mask + (size_t)row * Nc) : nullptr;
#pragma unroll
            for (int nt = 0; nt < 4; nt++) {
                int col = col_b + nt * 8;
                float v0 = acc[mt][nt][h * 2 + 0];
                float v1 = acc[mt][nt][h * 2 + 1];
                if (EPI == 1 || EPI == 2) { v0 += bias[col]; v1 += bias[col + 1]; }
                if (EPI == 2) {
                    v0 = 0.5f * v0 * (1.0f + erff(v0 * 0.7071067811865475f));
                    v1 = 0.5f * v1 * (1.0f + erff(v1 * 0.7071067811865475f));
                }
                if (EPI == 3) { v0 *= rsv; v1 *= rsv; }
                if (EPI == 4) {
                    int2 mk = *(const int2*)(Mr + col);
                    v0 = mk.x ? NEGV : v0 * QKSCALE;
                    v1 = mk.y ? NEGV : v1 * QKSCALE;
                }
                float2 o; o.x = v0; o.y = v1;
                *(float2*)(Cr + col) = o;
            }
        }
    }
}

// ================= transpose: out[C,R] = in[R,C]^T ==========================
__global__ void k_transpose(const float* __restrict__ in, float* __restrict__ out,
                            int R, int C) {
    __shared__ float t[32][33];
    int r0 = blockIdx.y * 32, c0 = blockIdx.x * 32;
    int x = threadIdx.x, y = threadIdx.y;
    for (int i = y; i < 32; i += 8)
        t[i][x] = in[(size_t)(r0 + i) * C + c0 + x];
    __syncthreads();
    for (int i = y; i < 32; i += 8)
        out[(size_t)(c0 + i) * R + r0 + x] = t[x][i];
}

// ================= drop_x build + x_init gather =============================
__global__ void k_drop(const float* __restrict__ x, const int* __restrict__ idx,
                       float* __restrict__ dx, float* __restrict__ out_init) {
    int r = blockIdx.x;
    const float* xr = x + (size_t)r * DD;
    float* dr = dx + (size_t)r * DD;
    for (int c = threadIdx.x; c < DD; c += blockDim.x) dr[c] = xr[c];
    __syncthreads();
    for (int g = threadIdx.x; g < GG; g += blockDim.x) {
        int c = idx[r * GG + g];
        out_init[r * GG + g] = xr[c];
        dr[c] = 0.0f;
    }
}

// ================= dual softmax combine =====================================
__global__ void k_softmax(float* __restrict__ Sr, const float* __restrict__ Sf,
                          float* __restrict__ rinv) {
    int r = blockIdx.x, tid = threadIdx.x;
    float* sr = Sr + (size_t)r * NTOK;
    const float* sf = Sf + (size_t)r * NTOK;
    __shared__ float red[256];
    float m = -3.4e38f;
    for (int j = tid * 4; j < NTOK; j += 1024) {
        float4 a = *(const float4*)&sr[j];
        float4 b = *(const float4*)&sf[j];
        m = fmaxf(m, fmaxf(fmaxf(a.x, a.y), fmaxf(a.z, a.w)));
        m = fmaxf(m, fmaxf(fmaxf(b.x, b.y), fmaxf(b.z, b.w)));
    }
    red[tid] = m; __syncthreads();
    for (int s = 128; s > 0; s >>= 1) {
        if (tid < s) red[tid] = fmaxf(red[tid], red[tid + s]);
        __syncthreads();
    }
    m = red[0]; __syncthreads();
    float sum = 0.0f;
    for (int j = tid * 4; j < NTOK; j += 1024) {
        float4 a = *(const float4*)&sr[j];
        float4 b = *(const float4*)&sf[j];
        float4 p;
        p.x = expf(a.x - m) + GAM * expf(b.x - m);
        p.y = expf(a.y - m) + GAM * expf(b.y - m);
        p.z = expf(a.z - m) + GAM * expf(b.z - m);
        p.w = expf(a.w - m) + GAM * expf(b.w - m);
        sum += p.x + p.y + p.z + p.w;
        *(float4*)&sr[j] = p;
    }
    red[tid] = sum; __syncthreads();
    for (int s = 128; s > 0; s >>= 1) {
        if (tid < s) red[tid] += red[tid + s];
        __syncthreads();
    }
    if (tid == 0) rinv[r] = 1.0f / red[0];
}

// ================= residual add + LayerNorm =================================
__global__ void k_addln(const float* __restrict__ a, const float* __restrict__ b,
                        const float* __restrict__ g, const float* __restrict__ bb,
                        float* __restrict__ out) {
    int r = blockIdx.x, tid = threadIdx.x;
    __shared__ float s1[128], s2[128];
    const float* ar = a + (size_t)r * DD;
    const float* br = b + (size_t)r * DD;
    float4 va = *(const float4*)&ar[tid * 4];
    float4 vb = *(const float4*)&br[tid * 4];
    float v0 = va.x + vb.x, v1 = va.y + vb.y, v2 = va.z + vb.z, v3 = va.w + vb.w;
    s1[tid] = v0 + v1 + v2 + v3;
    s2[tid] = v0 * v0 + v1 * v1 + v2 * v2 + v3 * v3;
    __syncthreads();
    for (int s = 64; s > 0; s >>= 1) {
        if (tid < s) { s1[tid] += s1[tid + s]; s2[tid] += s2[tid + s]; }
        __syncthreads();
    }
    float mu = s1[0] * (1.0f / DD);
    float var = s2[0] * (1.0f / DD) - mu * mu;
    float rstd = rsqrtf(var + 1e-5f);
    int c = tid * 4;
    float4 o;
    o.x = (v0 - mu) * rstd * g[c + 0] + bb[c + 0];
    o.y = (v1 - mu) * rstd * g[c + 1] + bb[c + 1];
    o.z = (v2 - mu) * rstd * g[c + 2] + bb[c + 2];
    o.w = (v3 - mu) * rstd * g[c + 3] + bb[c + 3];
    *(float4*)&out[(size_t)r * DD + c] = o;
}

// ================= final gather =============================================
__global__ void k_gather(const float* __restrict__ H, const int* __restrict__ idx,
                         float* __restrict__ out) {
    int r = blockIdx.x;
    for (int g = threadIdx.x; g < GG; g += blockDim.x)
        out[r * GG + g] = H[(size_t)r * DD + idx[r * GG + g]];
}

// ================= host side ================================================
template <int EPI>
static void mma_gemm(const float* A, const float* B, float* C, int M, int Nc, int K,
                     const float* bias = nullptr, const float* rs = nullptr,
                     const int* mask = nullptr) {
    dim3 g(Nc / 128, M / 128);
    k_mma_gemm<EPI><<<g, 256>>>(A, B, C, M, Nc, K, bias, rs, mask);
}

static void run_attention(const float* h,
                          const float* Wqr_t, const float* Wkr_t,
                          const float* Wqf_t, const float* Wkf_t, const float* Wv_t,
                          const int* rmask, const int* fmask,
                          float* q, float* k, float* qf, float* kf, float* v, float* vt,
                          float* Sr, float* Sf, float* rinv, float* outbuf) {
    mma_gemm<0>(h, Wqr_t, q,  NTOK, DD, DD);
    mma_gemm<0>(h, Wkr_t, k,  NTOK, DD, DD);
    mma_gemm<0>(h, Wqf_t, qf, NTOK, DD, DD);
    mma_gemm<0>(h, Wkf_t, kf, NTOK, DD, DD);
    mma_gemm<0>(h, Wv_t,  v,  NTOK, DD, DD);
    k_transpose<<<dim3(DD / 32, NTOK / 32), dim3(32, 8)>>>(v, vt, NTOK, DD);
    mma_gemm<4>(q,  k,  Sr, NTOK, NTOK, DD, nullptr, nullptr, rmask);
    mma_gemm<4>(qf, kf, Sf, NTOK, NTOK, DD, nullptr, nullptr, fmask);
    k_softmax<<<NTOK, 256>>>(Sr, Sf, rinv);
    mma_gemm<3>(Sr, vt, outbuf, NTOK, DD, NTOK, nullptr, rinv);
}

extern "C" void kernel_launch(void* const* d_in, const int* in_sizes, int n_in,
                              void* d_out, int out_size) {
    const float* x    = (const float*)d_in[0];
    const int*   idx  = (const int*)  d_in[1];
    const int*   rmsk = (const int*)  d_in[2];
    const int*   fmsk = (const int*)  d_in[3];
    const float* W[11] = {
        (const float*)d_in[4],  (const float*)d_in[5],  (const float*)d_in[6],
        (const float*)d_in[7],  (const float*)d_in[8],  (const float*)d_in[9],
        (const float*)d_in[10], (const float*)d_in[11], (const float*)d_in[12],
        (const float*)d_in[13], (const float*)d_in[24]  // head_W last
    };
    const float* fW1 = (const float*)d_in[14];
    const float* fb1 = (const float*)d_in[15];
    const float* fW2 = (const float*)d_in[16];
    const float* fb2 = (const float*)d_in[17];
    const float* l1g = (const float*)d_in[18];
    const float* l1b = (const float*)d_in[19];
    const float* l2g = (const float*)d_in[20];
    const float* l2b = (const float*)d_in[21];
    const float* l3g = (const float*)d_in[22];
    const float* l3b = (const float*)d_in[23];
    const float* hb  = (const float*)d_in[25];

    float* out       = (float*)d_out;
    float* out_init  = out;
    float* out_recon = out + (size_t)NTOK * GG;

    float *dropx, *q, *k, *qf, *kf, *v, *vt, *t0, *h1, *h2, *ffb, *Sr, *Sf, *rinv, *wt;
    cudaGetSymbolAddress((void**)&dropx, g_dropx);
    cudaGetSymbolAddress((void**)&q,  g_q);
    cudaGetSymbolAddress((void**)&k,  g_k);
    cudaGetSymbolAddress((void**)&qf, g_qf);
    cudaGetSymbolAddress((void**)&kf, g_kf);
    cudaGetSymbolAddress((void**)&v,  g_v);
    cudaGetSymbolAddress((void**)&vt, g_vt);
    cudaGetSymbolAddress((void**)&t0, g_t0);
    cudaGetSymbolAddress((void**)&h1, g_h1);
    cudaGetSymbolAddress((void**)&h2, g_h2);
    cudaGetSymbolAddress((void**)&ffb, g_ffb);
    cudaGetSymbolAddress((void**)&Sr, g_Sr);
    cudaGetSymbolAddress((void**)&Sf, g_Sf);
    cudaGetSymbolAddress((void**)&rinv, g_rinv);
    cudaGetSymbolAddress((void**)&wt, g_wt);

    // transpose all weights: W[K,N] -> Wt[N,K]
    float* Wt[11];
    for (int i = 0; i < 11; i++) {
        Wt[i] = wt + (size_t)i * DD * DD;
        k_transpose<<<dim3(DD / 32, DD / 32), dim3(32, 8)>>>(W[i], Wt[i], DD, DD);
    }
    float* fW1t = wt + (size_t)11 * DD * DD;            // [FFD, DD]
    float* fW2t = fW1t + (size_t)DD * FFD;              // [DD, FFD]
    k_transpose<<<dim3(FFD / 32, DD / 32), dim3(32, 8)>>>(fW1, fW1t, DD, FFD);
    k_transpose<<<dim3(DD / 32, FFD / 32), dim3(32, 8)>>>(fW2, fW2t, FFD, DD);

    // drop_x + x_init
    k_drop<<<NTOK, 128>>>(x, idx, dropx, out_init);

    // encoder attention
    run_attention(dropx, Wt[0], Wt[1], Wt[2], Wt[3], Wt[4], rmsk, fmsk,
                  q, k, qf, kf, v, vt, Sr, Sf, rinv, t0);
    k_addln<<<NTOK, 128>>>(t0, dropx, l1g, l1b, h1);

    // feed-forward
    mma_gemm<2>(h1, fW1t, ffb, NTOK, FFD, DD, fb1);
    mma_gemm<1>(ffb, fW2t, t0, NTOK, DD, FFD, fb2);
    k_addln<<<NTOK, 128>>>(t0, h1, l2g, l2b, h2);

    // decoder attention
    run_attention(h2, Wt[5], Wt[6], Wt[7], Wt[8], Wt[9], rmsk, fmsk,
                  q, k, qf, kf, v, vt, Sr, Sf, rinv, t0);
    k_addln<<<NTOK, 128>>>(t0, h2, l3g, l3b, h1);

    // head + x_recon gather
    mma_gemm<1>(h1, Wt[10], t0, NTOK, DD, DD, hb);
    k_gather<<<NTOK, 128>>>(t0, idx, out_recon);
}

// round 4
// speedup vs baseline: 1.9073x; 1.8272x over previous
#include <cuda_runtime.h>
#include <math.h>
#include <stdint.h>

#define NTOK 8192
#define DD   512
#define FFD  2048
#define GG   102
#define GAM  0.5f
#define NEGV (-1e9f)
#define QKSCALE 0.044194173824159216f   // 1/sqrt(512)

// ================= scratch (device globals; no allocation allowed) =========
static __device__ float g_dropx[NTOK * DD];
static __device__ float g_q [NTOK * DD];
static __device__ float g_k [NTOK * DD];
static __device__ float g_qf[NTOK * DD];
static __device__ float g_kf[NTOK * DD];
static __device__ float g_v [NTOK * DD];
static __device__ float g_vt[NTOK * DD];          // V transposed [DD, NTOK]
static __device__ float g_t0[NTOK * DD];
static __device__ float g_h1[NTOK * DD];
static __device__ float g_h2[NTOK * DD];
static __device__ float g_ffb[NTOK * FFD];
static __device__ float g_Sr[(size_t)NTOK * NTOK];   // 256 MB
static __device__ float g_Sf[(size_t)NTOK * NTOK];   // 256 MB
static __device__ float g_rinv[NTOK];
static __device__ float g_wt[11 * DD * DD + DD * FFD + FFD * DD];

// ================= helpers =================================================
__device__ __forceinline__ uint32_t f2tf32(float f) {
    uint32_t u;
    asm("cvt.rna.tf32.f32 %0, %1;" : "=r"(u) : "f"(f));
    return u;
}

__device__ __forceinline__ void mma_tf32(float* d, uint32_t a0, uint32_t a1,
                                         uint32_t a2, uint32_t a3,
                                         uint32_t b0, uint32_t b1) {
    asm volatile(
        "mma.sync.aligned.m16n8k8.row.col.f32.tf32.tf32.f32 "
        "{%0,%1,%2,%3}, {%4,%5,%6,%7}, {%8,%9}, {%0,%1,%2,%3};"
        : "+f"(d[0]), "+f"(d[1]), "+f"(d[2]), "+f"(d[3])
        : "r"(a0), "r"(a1), "r"(a2), "r"(a3), "r"(b0), "r"(b1));
}

// ================ mma.sync tf32 NT GEMM: C[M,Nc] = A[M,K] @ B[Nc,K]^T =======
// CTA tile 128x128, 256 threads, 8 warps (2m x 4n), warp tile 64x32,
// K chunks of 16, double-buffered SMEM with k-permuted + swizzled layout.
// EPI: 0 plain, 1 +bias, 2 +bias+GELU, 3 row-scale rs[m], 4 score mask+QKSCALE
template <int EPI>
__global__ void __launch_bounds__(256, 2) k_mma_gemm(
    const float* __restrict__ A, const float* __restrict__ B, float* __restrict__ C,
    int M, int Nc, int K,
    const float* __restrict__ bias, const float* __restrict__ rs,
    const int* __restrict__ mask)
{
    __shared__ uint32_t As[2][128 * 16];
    __shared__ uint32_t Bs[2][128 * 16];

    const int tid = threadIdx.x;
    const int wid = tid >> 5;
    const int lane = tid & 31;
    const int wm = wid >> 2;          // 0..1
    const int wn = wid & 3;           // 0..3
    const int bx = blockIdx.x, by = blockIdx.y;

    // staging role: threads 0-127 stage A rows, 128-255 stage B rows
    const int half = tid >> 7;
    const int r = tid & 127;
    const float* src = half ? (B + (size_t)(bx * 128 + r) * K)
                            : (A + (size_t)(by * 128 + r) * K);
    const int rot = (r >> 1) & 3;
    const int rowbase = r * 16;

    float acc[4][4][4];
#pragma unroll
    for (int i = 0; i < 4; i++)
#pragma unroll
        for (int j = 0; j < 4; j++)
#pragma unroll
            for (int q = 0; q < 4; q++) acc[i][j][q] = 0.0f;

    const int nch = K >> 4;

    // ---- stage chunk 0 ----
    {
        float4 f[4];
#pragma unroll
        for (int q = 0; q < 4; q++) f[q] = *(const float4*)(src + q * 4);
        uint32_t* dst = half ? &Bs[0][0] : &As[0][0];
#pragma unroll
        for (int g = 0; g < 4; g++) {
            uint4 pv;
            pv.x = f2tf32((&f[0].x)[g]);
            pv.y = f2tf32((&f[1].x)[g]);
            pv.z = f2tf32((&f[2].x)[g]);
            pv.w = f2tf32((&f[3].x)[g]);
            *(uint4*)&dst[rowbase + ((g ^ rot) << 2)] = pv;
        }
    }
    __syncthreads();

    for (int c = 0; c < nch; ++c) {
        const int s = c & 1;
        // prefetch next chunk to regs (held as raw floats through mma section)
        float4 f[4];
        if (c + 1 < nch) {
            const float* sp = src + (c + 1) * 16;
#pragma unroll
            for (int q = 0; q < 4; q++) f[q] = *(const float4*)(sp + q * 4);
        }

        // ---- B fragments (held across mt loop) ----
        uint4 fb[4];
#pragma unroll
        for (int nt = 0; nt < 4; nt++) {
            int nl = wn * 32 + nt * 8 + (lane >> 2);
            int g = (lane & 3) ^ ((nl >> 1) & 3);
            fb[nt] = *(const uint4*)&Bs[s][nl * 16 + (g << 2)];
        }

        // ---- mt loop: A fragments transient (8 regs) ----
#pragma unroll
        for (int mt = 0; mt < 4; mt++) {
            const int rl = wm * 64 + mt * 16 + (lane >> 2);
            const int g = (lane & 3) ^ ((rl >> 1) & 3);
            uint4 fa0 = *(const uint4*)&As[s][rl * 16 + (g << 2)];
            uint4 fa1 = *(const uint4*)&As[s][(rl + 8) * 16 + (g << 2)];
#pragma unroll
            for (int nt = 0; nt < 4; nt++) {
                mma_tf32(acc[mt][nt], fa0.x, fa1.x, fa0.y, fa1.y, fb[nt].x, fb[nt].y);
                mma_tf32(acc[mt][nt], fa0.z, fa1.z, fa0.w, fa1.w, fb[nt].z, fb[nt].w);
            }
        }

        // ---- convert + store next chunk into other buffer ----
        if (c + 1 < nch) {
            uint32_t* dst = half ? &Bs[s ^ 1][0] : &As[s ^ 1][0];
#pragma unroll
            for (int g = 0; g < 4; g++) {
                uint4 pv;
                pv.x = f2tf32((&f[0].x)[g]);
                pv.y = f2tf32((&f[1].x)[g]);
                pv.z = f2tf32((&f[2].x)[g]);
                pv.w = f2tf32((&f[3].x)[g]);
                *(uint4*)&dst[rowbase + ((g ^ rot) << 2)] = pv;
            }
        }
        __syncthreads();
    }

    // ---- epilogue ----
    const int col_b = bx * 128 + wn * 32 + (lane & 3) * 2;
#pragma unroll
    for (int mt = 0; mt < 4; mt++) {
#pragma unroll
        for (int h = 0; h < 2; h++) {
            int row = by * 128 + wm * 64 + mt * 16 + (lane >> 2) + h * 8;
            float rsv = (EPI == 3) ? rs[row] : 1.0f;
            float* Cr = C + (size_t)row * Nc;
            const int* Mr = (EPI == 4) ? (mask + (size_t)row * Nc) : nullptr;
#pragma unroll
            for (int nt = 0; nt < 4; nt++) {
                int col = col_b + nt * 8;
                float v0 = acc[mt][nt][h * 2 + 0];
                float v1 = acc[mt][nt][h * 2 + 1];
                if (EPI == 1 || EPI == 2) { v0 += bias[col]; v1 += bias[col + 1]; }
                if (EPI == 2) {
                    v0 = 0.5f * v0 * (1.0f + erff(v0 * 0.7071067811865475f));
                    v1 = 0.5f * v1 * (1.0f + erff(v1 * 0.7071067811865475f));
                }
                if (EPI == 3) { v0 *= rsv; v1 *= rsv; }
                if (EPI == 4) {
                    int2 mk = *(const int2*)(Mr + col);
                    v0 = mk.x ? NEGV : v0 * QKSCALE;
                    v1 = mk.y ? NEGV : v1 * QKSCALE;
                }
                float2 o; o.x = v0; o.y = v1;
                *(float2*)(Cr + col) = o;
            }
        }
    }
}

// ================= transpose: out[C,R] = in[R,C]^T ==========================
__global__ void k_transpose(const float* __restrict__ in, float* __restrict__ out,
                            int R, int C) {
    __shared__ float t[32][33];
    int r0 = blockIdx.y * 32, c0 = blockIdx.x * 32;
    int x = threadIdx.x, y = threadIdx.y;
    for (int i = y; i < 32; i += 8)
        t[i][x] = in[(size_t)(r0 + i) * C + c0 + x];
    __syncthreads();
    for (int i = y; i < 32; i += 8)
        out[(size_t)(c0 + i) * R + r0 + x] = t[x][i];
}

// ================= transpose ALL 13 weights in ONE launch ===================
struct TPList {
    const float* src[13];
    float*       dst[13];
    int          R[13];
    int          C[13];
};
__global__ void k_transpose_all(TPList L) {
    int z = blockIdx.z;
    int R = L.R[z], C = L.C[z];
    int r0 = blockIdx.y * 32, c0 = blockIdx.x * 32;
    if (r0 >= R || c0 >= C) return;
    const float* in = L.src[z];
    float* out = L.dst[z];
    __shared__ float t[32][33];
    int x = threadIdx.x, y = threadIdx.y;
    for (int i = y; i < 32; i += 8)
        t[i][x] = in[(size_t)(r0 + i) * C + c0 + x];
    __syncthreads();
    for (int i = y; i < 32; i += 8)
        out[(size_t)(c0 + i) * R + r0 + x] = t[x][i];
}

// ================= drop_x build + x_init gather =============================
__global__ void k_drop(const float* __restrict__ x, const int* __restrict__ idx,
                       float* __restrict__ dx, float* __restrict__ out_init) {
    int r = blockIdx.x;
    const float* xr = x + (size_t)r * DD;
    float* dr = dx + (size_t)r * DD;
    for (int c = threadIdx.x; c < DD; c += blockDim.x) dr[c] = xr[c];
    __syncthreads();
    for (int g = threadIdx.x; g < GG; g += blockDim.x) {
        int c = idx[r * GG + g];
        out_init[r * GG + g] = xr[c];
        dr[c] = 0.0f;
    }
}

// ================= dual softmax combine =====================================
__global__ void k_softmax(float* __restrict__ Sr, const float* __restrict__ Sf,
                          float* __restrict__ rinv) {
    int r = blockIdx.x, tid = threadIdx.x;
    float* sr = Sr + (size_t)r * NTOK;
    const float* sf = Sf + (size_t)r * NTOK;
    __shared__ float red[256];
    float m = -3.4e38f;
    for (int j = tid * 4; j < NTOK; j += 1024) {
        float4 a = *(const float4*)&sr[j];
        float4 b = *(const float4*)&sf[j];
        m = fmaxf(m, fmaxf(fmaxf(a.x, a.y), fmaxf(a.z, a.w)));
        m = fmaxf(m, fmaxf(fmaxf(b.x, b.y), fmaxf(b.z, b.w)));
    }
    red[tid] = m; __syncthreads();
    for (int s = 128; s > 0; s >>= 1) {
        if (tid < s) red[tid] = fmaxf(red[tid], red[tid + s]);
        __syncthreads();
    }
    m = red[0]; __syncthreads();
    float sum = 0.0f;
    for (int j = tid * 4; j < NTOK; j += 1024) {
        float4 a = *(const float4*)&sr[j];
        float4 b = *(const float4*)&sf[j];
        float4 p;
        p.x = expf(a.x - m) + GAM * expf(b.x - m);
        p.y = expf(a.y - m) + GAM * expf(b.y - m);
        p.z = expf(a.z - m) + GAM * expf(b.z - m);
        p.w = expf(a.w - m) + GAM * expf(b.w - m);
        sum += p.x + p.y + p.z + p.w;
        *(float4*)&sr[j] = p;
    }
    red[tid] = sum; __syncthreads();
    for (int s = 128; s > 0; s >>= 1) {
        if (tid < s) red[tid] += red[tid + s];
        __syncthreads();
    }
    if (tid == 0) rinv[r] = 1.0f / red[0];
}

// ================= residual add + LayerNorm =================================
__global__ void k_addln(const float* __restrict__ a, const float* __restrict__ b,
                        const float* __restrict__ g, const float* __restrict__ bb,
                        float* __restrict__ out) {
    int r = blockIdx.x, tid = threadIdx.x;
    __shared__ float s1[128], s2[128];
    const float* ar = a + (size_t)r * DD;
    const float* br = b + (size_t)r * DD;
    float4 va = *(const float4*)&ar[tid * 4];
    float4 vb = *(const float4*)&br[tid * 4];
    float v0 = va.x + vb.x, v1 = va.y + vb.y, v2 = va.z + vb.z, v3 = va.w + vb.w;
    s1[tid] = v0 + v1 + v2 + v3;
    s2[tid] = v0 * v0 + v1 * v1 + v2 * v2 + v3 * v3;
    __syncthreads();
    for (int s = 64; s > 0; s >>= 1) {
        if (tid < s) { s1[tid] += s1[tid + s]; s2[tid] += s2[tid + s]; }
        __syncthreads();
    }
    float mu = s1[0] * (1.0f / DD);
    float var = s2[0] * (1.0f / DD) - mu * mu;
    float rstd = rsqrtf(var + 1e-5f);
    int c = tid * 4;
    float4 o;
    o.x = (v0 - mu) * rstd * g[c + 0] + bb[c + 0];
    o.y = (v1 - mu) * rstd * g[c + 1] + bb[c + 1];
    o.z = (v2 - mu) * rstd * g[c + 2] + bb[c + 2];
    o.w = (v3 - mu) * rstd * g[c + 3] + bb[c + 3];
    *(float4*)&out[(size_t)r * DD + c] = o;
}

// ================= final gather =============================================
__global__ void k_gather(const float* __restrict__ H, const int* __restrict__ idx,
                         float* __restrict__ out) {
    int r = blockIdx.x;
    for (int g = threadIdx.x; g < GG; g += blockDim.x)
        out[r * GG + g] = H[(size_t)r * DD + idx[r * GG + g]];
}

// ================= host side ================================================
template <int EPI>
static void mma_gemm(const float* A, const float* B, float* C, int M, int Nc, int K,
                     const float* bias = nullptr, const float* rs = nullptr,
                     const int* mask = nullptr) {
    dim3 g(Nc / 128, M / 128);
    k_mma_gemm<EPI><<<g, 256>>>(A, B, C, M, Nc, K, bias, rs, mask);
}

static void run_attention(const float* h,
                          const float* Wqr_t, const float* Wkr_t,
                          const float* Wqf_t, const float* Wkf_t, const float* Wv_t,
                          const int* rmask, const int* fmask,
                          float* q, float* k, float* qf, float* kf, float* v, float* vt,
                          float* Sr, float* Sf, float* rinv, float* outbuf) {
    mma_gemm<0>(h, Wqr_t, q,  NTOK, DD, DD);
    mma_gemm<0>(h, Wkr_t, k,  NTOK, DD, DD);
    mma_gemm<0>(h, Wqf_t, qf, NTOK, DD, DD);
    mma_gemm<0>(h, Wkf_t, kf, NTOK, DD, DD);
    mma_gemm<0>(h, Wv_t,  v,  NTOK, DD, DD);
    k_transpose<<<dim3(DD / 32, NTOK / 32), dim3(32, 8)>>>(v, vt, NTOK, DD);
    mma_gemm<4>(q,  k,  Sr, NTOK, NTOK, DD, nullptr, nullptr, rmask);
    mma_gemm<4>(qf, kf, Sf, NTOK, NTOK, DD, nullptr, nullptr, fmask);
    k_softmax<<<NTOK, 256>>>(Sr, Sf, rinv);
    mma_gemm<3>(Sr, vt, outbuf, NTOK, DD, NTOK, nullptr, rinv);
}

extern "C" void kernel_launch(void* const* d_in, const int* in_sizes, int n_in,
                              void* d_out, int out_size) {
    const float* x    = (const float*)d_in[0];
    const int*   idx  = (const int*)  d_in[1];
    const int*   rmsk = (const int*)  d_in[2];
    const int*   fmsk = (const int*)  d_in[3];
    const float* W[11] = {
        (const float*)d_in[4],  (const float*)d_in[5],  (const float*)d_in[6],
        (const float*)d_in[7],  (const float*)d_in[8],  (const float*)d_in[9],
        (const float*)d_in[10], (const float*)d_in[11], (const float*)d_in[12],
        (const float*)d_in[13], (const float*)d_in[24]  // head_W last
    };
    const float* fW1 = (const float*)d_in[14];
    const float* fb1 = (const float*)d_in[15];
    const float* fW2 = (const float*)d_in[16];
    const float* fb2 = (const float*)d_in[17];
    const float* l1g = (const float*)d_in[18];
    const float* l1b = (const float*)d_in[19];
    const float* l2g = (const float*)d_in[20];
    const float* l2b = (const float*)d_in[21];
    const float* l3g = (const float*)d_in[22];
    const float* l3b = (const float*)d_in[23];
    const float* hb  = (const float*)d_in[25];

    float* out       = (float*)d_out;
    float* out_init  = out;
    float* out_recon = out + (size_t)NTOK * GG;

    float *dropx, *q, *k, *qf, *kf, *v, *vt, *t0, *h1, *h2, *ffb, *Sr, *Sf, *rinv, *wt;
    cudaGetSymbolAddress((void**)&dropx, g_dropx);
    cudaGetSymbolAddress((void**)&q,  g_q);
    cudaGetSymbolAddress((void**)&k,  g_k);
    cudaGetSymbolAddress((void**)&qf, g_qf);
    cudaGetSymbolAddress((void**)&kf, g_kf);
    cudaGetSymbolAddress((void**)&v,  g_v);
    cudaGetSymbolAddress((void**)&vt, g_vt);
    cudaGetSymbolAddress((void**)&t0, g_t0);
    cudaGetSymbolAddress((void**)&h1, g_h1);
    cudaGetSymbolAddress((void**)&h2, g_h2);
    cudaGetSymbolAddress((void**)&ffb, g_ffb);
    cudaGetSymbolAddress((void**)&Sr, g_Sr);
    cudaGetSymbolAddress((void**)&Sf, g_Sf);
    cudaGetSymbolAddress((void**)&rinv, g_rinv);
    cudaGetSymbolAddress((void**)&wt, g_wt);

    // transposed weight destinations
    float* Wt[11];
    for (int i = 0; i < 11; i++) Wt[i] = wt + (size_t)i * DD * DD;
    float* fW1t = wt + (size_t)11 * DD * DD;            // [FFD, DD]
    float* fW2t = fW1t + (size_t)DD * FFD;              // [DD, FFD]

    // ---- launch 0: all 13 weight transposes in one kernel ----
    TPList L;
    for (int i = 0; i < 11; i++) {
        L.src[i] = W[i]; L.dst[i] = Wt[i]; L.R[i] = DD; L.C[i] = DD;
    }
    L.src[11] = fW1; L.dst[11] = fW1t; L.R[11] = DD;  L.C[11] = FFD;
    L.src[12] = fW2; L.dst[12] = fW2t; L.R[12] = FFD; L.C[12] = DD;
    k_transpose_all<<<dim3(64, 64, 13), dim3(32, 8)>>>(L);

    // ---- launch 1: drop_x + x_init ----
    k_drop<<<NTOK, 128>>>(x, idx, dropx, out_init);

    // encoder attention (launches 2..6 are projection GEMMs; #5 profiled)
    run_attention(dropx, Wt[0], Wt[1], Wt[2], Wt[3], Wt[4], rmsk, fmsk,
                  q, k, qf, kf, v, vt, Sr, Sf, rinv, t0);
    k_addln<<<NTOK, 128>>>(t0, dropx, l1g, l1b, h1);

    // feed-forward
    mma_gemm<2>(h1, fW1t, ffb, NTOK, FFD, DD, fb1);
    mma_gemm<1>(ffb, fW2t, t0, NTOK, DD, FFD, fb2);
    k_addln<<<NTOK, 128>>>(t0, h1, l2g, l2b, h2);

    // decoder attention
    run_attention(h2, Wt[5], Wt[6], Wt[7], Wt[8], Wt[9], rmsk, fmsk,
                  q, k, qf, kf, v, vt, Sr, Sf, rinv, t0);
    k_addln<<<NTOK, 128>>>(t0, h2, l3g, l3b, h1);

    // head + x_recon gather
    mma_gemm<1>(h1, Wt[10], t0, NTOK, DD, DD, hb);
    k_gather<<<NTOK, 128>>>(t0, idx, out_recon);
}

// round 6
// speedup vs baseline: 1.9587x; 1.0269x over previous
#include <cuda_runtime.h>
#include <math.h>
#include <stdint.h>

#define NTOK 8192
#define DD   512
#define FFD  2048
#define GG   102
#define GAM  0.5f
#define NEGV (-1e9f)
#define QKSCALE 0.044194173824159216f   // 1/sqrt(512)

// ================= scratch (device globals; no allocation allowed) =========
static __device__ float g_dropx [NTOK * DD];
static __device__ float g_dropxr[NTOK * DD];     // tf32-rounded copy
static __device__ float g_q [NTOK * DD];
static __device__ float g_k [NTOK * DD];
static __device__ float g_qf[NTOK * DD];
static __device__ float g_kf[NTOK * DD];
static __device__ float g_v [NTOK * DD];
static __device__ float g_vt[NTOK * DD];          // V^T rounded [DD, NTOK]
static __device__ float g_t0[NTOK * DD];
static __device__ float g_h1 [NTOK * DD];
static __device__ float g_h1r[NTOK * DD];
static __device__ float g_h2 [NTOK * DD];
static __device__ float g_h2r[NTOK * DD];
static __device__ float g_ffb[NTOK * FFD];
static __device__ float g_Sr[(size_t)NTOK * NTOK];   // 256 MB
static __device__ float g_Sf[(size_t)NTOK * NTOK];   // 256 MB
static __device__ float g_rinv[NTOK];
static __device__ float g_wt[11 * DD * DD + DD * FFD + FFD * DD];

// ================= helpers =================================================
__device__ __forceinline__ float rnd_tf32(float f) {
    uint32_t u;
    asm("cvt.rna.tf32.f32 %0, %1;" : "=r"(u) : "f"(f));
    return __uint_as_float(u);
}

__device__ __forceinline__ void mma_tf32(float* d, uint32_t a0, uint32_t a1,
                                         uint32_t a2, uint32_t a3,
                                         uint32_t b0, uint32_t b1) {
    asm volatile(
        "mma.sync.aligned.m16n8k8.row.col.f32.tf32.tf32.f32 "
        "{%0,%1,%2,%3}, {%4,%5,%6,%7}, {%8,%9}, {%0,%1,%2,%3};"
        : "+f"(d[0]), "+f"(d[1]), "+f"(d[2]), "+f"(d[3])
        : "r"(a0), "r"(a1), "r"(a2), "r"(a3), "r"(b0), "r"(b1));
}

// ================ mma.sync tf32 NT GEMM: C[M,Nc] = A[M,K] @ B[Nc,K]^T =======
// Inputs MUST already be tf32-rounded f32. CTA tile 128x128, 128 threads,
// 4 warps (2m x 2n), warp tile 64x64, K chunks of 16, double-buffered SMEM
// with k-permuted + XOR-swizzled layout (word g of each float4 gathered).
// EPI: 0 plain, 1 +bias, 2 +bias+GELU, 3 row-scale rs[m], 4 score mask+scale
// RND: round output to tf32 (for values feeding another GEMM)
template <int EPI, int RND>
__global__ void __launch_bounds__(128, 2) k_mma_gemm(
    const float* __restrict__ A, const float* __restrict__ B, float* __restrict__ C,
    int M, int Nc, int K,
    const float* __restrict__ bias, const float* __restrict__ rs,
    const int* __restrict__ mask)
{
    __shared__ uint32_t As[2][128 * 16];
    __shared__ uint32_t Bs[2][128 * 16];

    const int tid = threadIdx.x;          // 0..127
    const int wid = tid >> 5;             // 0..3
    const int lane = tid & 31;
    const int wm = wid >> 1;              // 0..1
    const int wn = wid & 1;               // 0..1
    const int bx = blockIdx.x, by = blockIdx.y;

    // each thread stages one A row and one B row (16 words each per chunk)
    const float* srcA = A + (size_t)(by * 128 + tid) * K;
    const float* srcB = B + (size_t)(bx * 128 + tid) * K;
    const int rot = (tid >> 1) & 3;
    const int rowbase = tid * 16;

    float acc[4][8][4];
#pragma unroll
    for (int i = 0; i < 4; i++)
#pragma unroll
        for (int j = 0; j < 8; j++)
#pragma unroll
            for (int q = 0; q < 4; q++) acc[i][j][q] = 0.0f;

    const int nch = K >> 4;

    // ---- stage chunk 0 ----
    {
        float4 fa[4], fb[4];
#pragma unroll
        for (int q = 0; q < 4; q++) fa[q] = *(const float4*)(srcA + q * 4);
#pragma unroll
        for (int q = 0; q < 4; q++) fb[q] = *(const float4*)(srcB + q * 4);
#pragma unroll
        for (int g = 0; g < 4; g++) {
            uint4 pa, pb;
            pa.x = __float_as_uint((&fa[0].x)[g]); pa.y = __float_as_uint((&fa[1].x)[g]);
            pa.z = __float_as_uint((&fa[2].x)[g]); pa.w = __float_as_uint((&fa[3].x)[g]);
            pb.x = __float_as_uint((&fb[0].x)[g]); pb.y = __float_as_uint((&fb[1].x)[g]);
            pb.z = __float_as_uint((&fb[2].x)[g]); pb.w = __float_as_uint((&fb[3].x)[g]);
            *(uint4*)&As[0][rowbase + ((g ^ rot) << 2)] = pa;
            *(uint4*)&Bs[0][rowbase + ((g ^ rot) << 2)] = pb;
        }
    }
    __syncthreads();

    for (int c = 0; c < nch; ++c) {
        const int s = c & 1;
        // prefetch next chunk to regs
        float4 pfa[4], pfb[4];
        if (c + 1 < nch) {
            const float* spA = srcA + (c + 1) * 16;
            const float* spB = srcB + (c + 1) * 16;
#pragma unroll
            for (int q = 0; q < 4; q++) pfa[q] = *(const float4*)(spA + q * 4);
#pragma unroll
            for (int q = 0; q < 4; q++) pfb[q] = *(const float4*)(spB + q * 4);
        }

        // ---- B fragments: 8 n8-tiles, held across mt loop ----
        uint4 fb[8];
#pragma unroll
        for (int nt = 0; nt < 8; nt++) {
            int nl = wn * 64 + nt * 8 + (lane >> 2);
            int g = (lane & 3) ^ ((nl >> 1) & 3);
            fb[nt] = *(const uint4*)&Bs[s][nl * 16 + (g << 2)];
        }

        // ---- mt loop: A fragments transient ----
#pragma unroll
        for (int mt = 0; mt < 4; mt++) {
            const int rl = wm * 64 + mt * 16 + (lane >> 2);
            const int g = (lane & 3) ^ ((rl >> 1) & 3);
            uint4 fa0 = *(const uint4*)&As[s][rl * 16 + (g << 2)];
            uint4 fa1 = *(const uint4*)&As[s][(rl + 8) * 16 + (g << 2)];
#pragma unroll
            for (int nt = 0; nt < 8; nt++) {
                mma_tf32(acc[mt][nt], fa0.x, fa1.x, fa0.y, fa1.y, fb[nt].x, fb[nt].y);
                mma_tf32(acc[mt][nt], fa0.z, fa1.z, fa0.w, fa1.w, fb[nt].z, fb[nt].w);
            }
        }

        // ---- store next chunk into other buffer ----
        if (c + 1 < nch) {
#pragma unroll
            for (int g = 0; g < 4; g++) {
                uint4 pa, pb;
                pa.x = __float_as_uint((&pfa[0].x)[g]); pa.y = __float_as_uint((&pfa[1].x)[g]);
                pa.z = __float_as_uint((&pfa[2].x)[g]); pa.w = __float_as_uint((&pfa[3].x)[g]);
                pb.x = __float_as_uint((&pfb[0].x)[g]); pb.y = __float_as_uint((&pfb[1].x)[g]);
                pb.z = __float_as_uint((&pfb[2].x)[g]); pb.w = __float_as_uint((&pfb[3].x)[g]);
                *(uint4*)&As[s ^ 1][rowbase + ((g ^ rot) << 2)] = pa;
                *(uint4*)&Bs[s ^ 1][rowbase + ((g ^ rot) << 2)] = pb;
            }
        }
        __syncthreads();
    }

    // ---- epilogue ----
    const int col_b = bx * 128 + wn * 64 + (lane & 3) * 2;
#pragma unroll
    for (int mt = 0; mt < 4; mt++) {
#pragma unroll
        for (int h = 0; h < 2; h++) {
            int row = by * 128 + wm * 64 + mt * 16 + (lane >> 2) + h * 8;
            float rsv = (EPI == 3) ? rs[row] : 1.0f;
            float* Cr = C + (size_t)row * Nc;
            const int* Mr = (EPI == 4) ? (mask + (size_t)row * Nc) : nullptr;
#pragma unroll
            for (int nt = 0; nt < 8; nt++) {
                int col = col_b + nt * 8;
                float v0 = acc[mt][nt][h * 2 + 0];
                float v1 = acc[mt][nt][h * 2 + 1];
                if (EPI == 1 || EPI == 2) { v0 += bias[col]; v1 += bias[col + 1]; }
                if (EPI == 2) {
                    v0 = 0.5f * v0 * (1.0f + erff(v0 * 0.7071067811865475f));
                    v1 = 0.5f * v1 * (1.0f + erff(v1 * 0.7071067811865475f));
                }
                if (EPI == 3) { v0 *= rsv; v1 *= rsv; }
                if (EPI == 4) {
                    int2 mk = *(const int2*)(Mr + col);
                    v0 = mk.x ? NEGV : v0 * QKSCALE;
                    v1 = mk.y ? NEGV : v1 * QKSCALE;
                }
                if (RND) { v0 = rnd_tf32(v0); v1 = rnd_tf32(v1); }
                float2 o; o.x = v0; o.y = v1;
                *(float2*)(Cr + col) = o;
            }
        }
    }
}

// ================= transpose (rounded): out[C,R] = tf32(in[R,C]^T) ==========
__global__ void k_transpose(const float* __restrict__ in, float* __restrict__ out,
                            int R, int C) {
    __shared__ float t[32][33];
    int r0 = blockIdx.y * 32, c0 = blockIdx.x * 32;
    int x = threadIdx.x, y = threadIdx.y;
    for (int i = y; i < 32; i += 8)
        t[i][x] = in[(size_t)(r0 + i) * C + c0 + x];
    __syncthreads();
    for (int i = y; i < 32; i += 8)
        out[(size_t)(c0 + i) * R + r0 + x] = rnd_tf32(t[x][i]);
}

// ================= transpose ALL 13 weights (rounded) in ONE launch =========
struct TPList {
    const float* src[13];
    float*       dst[13];
    int          R[13];
    int          C[13];
};
__global__ void k_transpose_all(TPList L) {
    int z = blockIdx.z;
    int R = L.R[z], C = L.C[z];
    int r0 = blockIdx.y * 32, c0 = blockIdx.x * 32;
    if (r0 >= R || c0 >= C) return;
    const float* in = L.src[z];
    float* out = L.dst[z];
    __shared__ float t[32][33];
    int x = threadIdx.x, y = threadIdx.y;
    for (int i = y; i < 32; i += 8)
        t[i][x] = in[(size_t)(r0 + i) * C + c0 + x];
    __syncthreads();
    for (int i = y; i < 32; i += 8)
        out[(size_t)(c0 + i) * R + r0 + x] = rnd_tf32(t[x][i]);
}

// ================= drop_x build (+rounded) + x_init gather ==================
__global__ void k_drop(const float* __restrict__ x, const int* __restrict__ idx,
                       float* __restrict__ dx, float* __restrict__ dxr,
                       float* __restrict__ out_init) {
    int r = blockIdx.x;
    const float* xr = x + (size_t)r * DD;
    float* dr  = dx  + (size_t)r * DD;
    float* drr = dxr + (size_t)r * DD;
    for (int c = threadIdx.x; c < DD; c += blockDim.x) {
        float v = xr[c];
        dr[c] = v;
        drr[c] = rnd_tf32(v);
    }
    __syncthreads();
    for (int g = threadIdx.x; g < GG; g += blockDim.x) {
        int c = idx[r * GG + g];
        out_init[r * GG + g] = xr[c];
        dr[c] = 0.0f;
        drr[c] = 0.0f;
    }
}

// ================= dual softmax combine (stores rounded probs) ==============
__global__ void k_softmax(float* __restrict__ Sr, const float* __restrict__ Sf,
                          float* __restrict__ rinv) {
    int r = blockIdx.x, tid = threadIdx.x;
    float* sr = Sr + (size_t)r * NTOK;
    const float* sf = Sf + (size_t)r * NTOK;
    __shared__ float red[256];
    float m = -3.4e38f;
    for (int j = tid * 4; j < NTOK; j += 1024) {
        float4 a = *(const float4*)&sr[j];
        float4 b = *(const float4*)&sf[j];
        m = fmaxf(m, fmaxf(fmaxf(a.x, a.y), fmaxf(a.z, a.w)));
        m = fmaxf(m, fmaxf(fmaxf(b.x, b.y), fmaxf(b.z, b.w)));
    }
    red[tid] = m; __syncthreads();
    for (int s = 128; s > 0; s >>= 1) {
        if (tid < s) red[tid] = fmaxf(red[tid], red[tid + s]);
        __syncthreads();
    }
    m = red[0]; __syncthreads();
    float sum = 0.0f;
    for (int j = tid * 4; j < NTOK; j += 1024) {
        float4 a = *(const float4*)&sr[j];
        float4 b = *(const float4*)&sf[j];
        float4 p;
        p.x = expf(a.x - m) + GAM * expf(b.x - m);
        p.y = expf(a.y - m) + GAM * expf(b.y - m);
        p.z = expf(a.z - m) + GAM * expf(b.z - m);
        p.w = expf(a.w - m) + GAM * expf(b.w - m);
        sum += p.x + p.y + p.z + p.w;
        p.x = rnd_tf32(p.x); p.y = rnd_tf32(p.y);
        p.z = rnd_tf32(p.z); p.w = rnd_tf32(p.w);
        *(float4*)&sr[j] = p;
    }
    red[tid] = sum; __syncthreads();
    for (int s = 128; s > 0; s >>= 1) {
        if (tid < s) red[tid] += red[tid + s];
        __syncthreads();
    }
    if (tid == 0) rinv[r] = 1.0f / red[0];
}

// ================= residual add + LayerNorm (+rounded copy) =================
__global__ void k_addln(const float* __restrict__ a, const float* __restrict__ b,
                        const float* __restrict__ g, const float* __restrict__ bb,
                        float* __restrict__ out, float* __restrict__ outr) {
    int r = blockIdx.x, tid = threadIdx.x;
    __shared__ float s1[128], s2[128];
    const float* ar = a + (size_t)r * DD;
    const float* br = b + (size_t)r * DD;
    float4 va = *(const float4*)&ar[tid * 4];
    float4 vb = *(const float4*)&br[tid * 4];
    float v0 = va.x + vb.x, v1 = va.y + vb.y, v2 = va.z + vb.z, v3 = va.w + vb.w;
    s1[tid] = v0 + v1 + v2 + v3;
    s2[tid] = v0 * v0 + v1 * v1 + v2 * v2 + v3 * v3;
    __syncthreads();
    for (int s = 64; s > 0; s >>= 1) {
        if (tid < s) { s1[tid] += s1[tid + s]; s2[tid] += s2[tid + s]; }
        __syncthreads();
    }
    float mu = s1[0] * (1.0f / DD);
    float var = s2[0] * (1.0f / DD) - mu * mu;
    float rstd = rsqrtf(var + 1e-5f);
    int c = tid * 4;
    float4 o;
    o.x = (v0 - mu) * rstd * g[c + 0] + bb[c + 0];
    o.y = (v1 - mu) * rstd * g[c + 1] + bb[c + 1];
    o.z = (v2 - mu) * rstd * g[c + 2] + bb[c + 2];
    o.w = (v3 - mu) * rstd * g[c + 3] + bb[c + 3];
    *(float4*)&out[(size_t)r * DD + c] = o;
    float4 orr;
    orr.x = rnd_tf32(o.x); orr.y = rnd_tf32(o.y);
    orr.z = rnd_tf32(o.z); orr.w = rnd_tf32(o.w);
    *(float4*)&outr[(size_t)r * DD + c] = orr;
}

// ================= final gather =============================================
__global__ void k_gather(const float* __restrict__ H, const int* __restrict__ idx,
                         float* __restrict__ out) {
    int r = blockIdx.x;
    for (int g = threadIdx.x; g < GG; g += blockDim.x)
        out[r * GG + g] = H[(size_t)r * DD + idx[r * GG + g]];
}

// ================= host side ================================================
template <int EPI, int RND>
static void mma_gemm(const float* A, const float* B, float* C, int M, int Nc, int K,
                     const float* bias = nullptr, const float* rs = nullptr,
                     const int* mask = nullptr) {
    dim3 g(Nc / 128, M / 128);
    k_mma_gemm<EPI, RND><<<g, 128>>>(A, B, C, M, Nc, K, bias, rs, mask);
}

static void run_attention(const float* hr,
                          const float* Wqr_t, const float* Wkr_t,
                          const float* Wqf_t, const float* Wkf_t, const float* Wv_t,
                          const int* rmask, const int* fmask,
                          float* q, float* k, float* qf, float* kf, float* v, float* vt,
                          float* Sr, float* Sf, float* rinv, float* outbuf) {
    mma_gemm<0, 1>(hr, Wqr_t, q,  NTOK, DD, DD);
    mma_gemm<0, 1>(hr, Wkr_t, k,  NTOK, DD, DD);
    mma_gemm<0, 1>(hr, Wqf_t, qf, NTOK, DD, DD);
    mma_gemm<0, 1>(hr, Wkf_t, kf, NTOK, DD, DD);
    mma_gemm<0, 0>(hr, Wv_t,  v,  NTOK, DD, DD);
    k_transpose<<<dim3(DD / 32, NTOK / 32), dim3(32, 8)>>>(v, vt, NTOK, DD);
    mma_gemm<4, 0>(q,  k,  Sr, NTOK, NTOK, DD, nullptr, nullptr, rmask);
    mma_gemm<4, 0>(qf, kf, Sf, NTOK, NTOK, DD, nullptr, nullptr, fmask);
    k_softmax<<<NTOK, 256>>>(Sr, Sf, rinv);
    mma_gemm<3, 0>(Sr, vt, outbuf, NTOK, DD, NTOK, nullptr, rinv);
}

extern "C" void kernel_launch(void* const* d_in, const int* in_sizes, int n_in,
                              void* d_out, int out_size) {
    const float* x    = (const float*)d_in[0];
    const int*   idx  = (const int*)  d_in[1];
    const int*   rmsk = (const int*)  d_in[2];
    const int*   fmsk = (const int*)  d_in[3];
    const float* W[11] = {
        (const float*)d_in[4],  (const float*)d_in[5],  (const float*)d_in[6],
        (const float*)d_in[7],  (const float*)d_in[8],  (const float*)d_in[9],
        (const float*)d_in[10], (const float*)d_in[11], (const float*)d_in[12],
        (const float*)d_in[13], (const float*)d_in[24]  // head_W last
    };
    const float* fW1 = (const float*)d_in[14];
    const float* fb1 = (const float*)d_in[15];
    const float* fW2 = (const float*)d_in[16];
    const float* fb2 = (const float*)d_in[17];
    const float* l1g = (const float*)d_in[18];
    const float* l1b = (const float*)d_in[19];
    const float* l2g = (const float*)d_in[20];
    const float* l2b = (const float*)d_in[21];
    const float* l3g = (const float*)d_in[22];
    const float* l3b = (const float*)d_in[23];
    const float* hb  = (const float*)d_in[25];

    float* out       = (float*)d_out;
    float* out_init  = out;
    float* out_recon = out + (size_t)NTOK * GG;

    float *dropx, *dropxr, *q, *k, *qf, *kf, *v, *vt, *t0;
    float *h1, *h1r, *h2, *h2r, *ffb, *Sr, *Sf, *rinv, *wt;
    cudaGetSymbolAddress((void**)&dropx,  g_dropx);
    cudaGetSymbolAddress((void**)&dropxr, g_dropxr);
    cudaGetSymbolAddress((void**)&q,  g_q);
    cudaGetSymbolAddress((void**)&k,  g_k);
    cudaGetSymbolAddress((void**)&qf, g_qf);
    cudaGetSymbolAddress((void**)&kf, g_kf);
    cudaGetSymbolAddress((void**)&v,  g_v);
    cudaGetSymbolAddress((void**)&vt, g_vt);
    cudaGetSymbolAddress((void**)&t0, g_t0);
    cudaGetSymbolAddress((void**)&h1,  g_h1);
    cudaGetSymbolAddress((void**)&h1r, g_h1r);
    cudaGetSymbolAddress((void**)&h2,  g_h2);
    cudaGetSymbolAddress((void**)&h2r, g_h2r);
    cudaGetSymbolAddress((void**)&ffb, g_ffb);
    cudaGetSymbolAddress((void**)&Sr, g_Sr);
    cudaGetSymbolAddress((void**)&Sf, g_Sf);
    cudaGetSymbolAddress((void**)&rinv, g_rinv);
    cudaGetSymbolAddress((void**)&wt, g_wt);

    // transposed (rounded) weight destinations
    float* Wt[11];
    for (int i = 0; i < 11; i++) Wt[i] = wt + (size_t)i * DD * DD;
    float* fW1t = wt + (size_t)11 * DD * DD;            // [FFD, DD]
    float* fW2t = fW1t + (size_t)DD * FFD;              // [DD, FFD]

    // ---- launch 0: all 13 weight transposes (rounded) in one kernel ----
    TPList L;
    for (int i = 0; i < 11; i++) {
        L.src[i] = W[i]; L.dst[i] = Wt[i]; L.R[i] = DD; L.C[i] = DD;
    }
    L.src[11] = fW1; L.dst[11] = fW1t; L.R[11] = DD;  L.C[11] = FFD;
    L.src[12] = fW2; L.dst[12] = fW2t; L.R[12] = FFD; L.C[12] = DD;
    k_transpose_all<<<dim3(64, 64, 13), dim3(32, 8)>>>(L);

    // ---- launch 1: drop_x (+rounded) + x_init ----
    k_drop<<<NTOK, 128>>>(x, idx, dropx, dropxr, out_init);

    // encoder attention
    run_attention(dropxr, Wt[0], Wt[1], Wt[2], Wt[3], Wt[4], rmsk, fmsk,
                  q, k, qf, kf, v, vt, Sr, Sf, rinv, t0);
    k_addln<<<NTOK, 128>>>(t0, dropx, l1g, l1b, h1, h1r);

    // feed-forward
    mma_gemm<2, 1>(h1r, fW1t, ffb, NTOK, FFD, DD, fb1);
    mma_gemm<1, 0>(ffb, fW2t, t0, NTOK, DD, FFD, fb2);
    k_addln<<<NTOK, 128>>>(t0, h1, l2g, l2b, h2, h2r);

    // decoder attention
    run_attention(h2r, Wt[5], Wt[6], Wt[7], Wt[8], Wt[9], rmsk, fmsk,
                  q, k, qf, kf, v, vt, Sr, Sf, rinv, t0);
    k_addln<<<NTOK, 128>>>(t0, h2, l3g, l3b, h1, h1r);

    // head + x_recon gather
    mma_gemm<1, 0>(h1r, Wt[10], t0, NTOK, DD, DD, hb);
    k_gather<<<NTOK, 128>>>(t0, idx, out_recon);
}

// round 10
// speedup vs baseline: 2.1269x; 1.0859x over previous
#include <cuda_runtime.h>
#include <math.h>
#include <stdint.h>

#define NTOK 8192
#define DD   512
#define FFD  2048
#define GG   102
#define GAM  0.5f
#define NEGV (-1e9f)
#define QKSCALE 0.044194173824159216f   // 1/sqrt(512)

// Global "GEMM-ready" layout: within each row's 16-word chunk,
// stored[g*4 + j] = orig[4*j + g]  (g = k%4, j = k/4).
// Staging to SMEM is then an identity 16B copy (cp.async-able), and a single
// LDS.128 of group g yields original k = {g, g+4, g+8, g+12} for the mma.

// ================= scratch (device globals; no allocation allowed) =========
static __device__ float g_dropx [NTOK * DD];
static __device__ float g_dropxr[NTOK * DD];     // tf32-rounded, permuted
static __device__ float g_q [NTOK * DD];
static __device__ float g_k [NTOK * DD];
static __device__ float g_qf[NTOK * DD];
static __device__ float g_kf[NTOK * DD];
static __device__ float g_v [NTOK * DD];          // normal layout
static __device__ float g_vt[NTOK * DD];          // V^T rounded+permuted [DD, NTOK]
static __device__ float g_t0[NTOK * DD];
static __device__ float g_h1 [NTOK * DD];
static __device__ float g_h1r[NTOK * DD];         // rounded+permuted
static __device__ float g_h2 [NTOK * DD];
static __device__ float g_h2r[NTOK * DD];
static __device__ float g_ffb[NTOK * FFD];        // rounded+permuted
static __device__ float g_Sr[(size_t)NTOK * NTOK];   // permuted cols
static __device__ float g_Sf[(size_t)NTOK * NTOK];   // permuted cols
static __device__ float g_rinv[NTOK];
static __device__ float g_wt[11 * DD * DD + DD * FFD + FFD * DD];  // rounded+permuted

// ================= helpers =================================================
__device__ __forceinline__ float rnd_tf32(float f) {
    uint32_t u;
    asm("cvt.rna.tf32.f32 %0, %1;" : "=r"(u) : "f"(f));
    return __uint_as_float(u);
}
__device__ __forceinline__ int pi16(int c) {   // permuted index within row
    return (c & ~15) | ((c & 3) << 2) | ((c & 15) >> 2);
}
__device__ __forceinline__ uint32_t smem_u32(const void* p) {
    uint32_t a;
    asm("{ .reg .u64 t; cvta.to.shared.u64 t, %1; cvt.u32.u64 %0, t; }" : "=r"(a) : "l"(p));
    return a;
}
#define CP_ASYNC16(dst, src) \
    asm volatile("cp.async.cg.shared.global [%0], [%1], 16;" :: "r"(dst), "l"(src) : "memory")
#define CP_COMMIT()  asm volatile("cp.async.commit_group;" ::: "memory")
#define CP_WAIT2()   asm volatile("cp.async.wait_group 2;" ::: "memory")

__device__ __forceinline__ void mma_tf32(float* d, uint32_t a0, uint32_t a1,
                                         uint32_t a2, uint32_t a3,
                                         uint32_t b0, uint32_t b1) {
    asm volatile(
        "mma.sync.aligned.m16n8k8.row.col.f32.tf32.tf32.f32 "
        "{%0,%1,%2,%3}, {%4,%5,%6,%7}, {%8,%9}, {%0,%1,%2,%3};"
        : "+f"(d[0]), "+f"(d[1]), "+f"(d[2]), "+f"(d[3])
        : "r"(a0), "r"(a1), "r"(a2), "r"(a3), "r"(b0), "r"(b1));
}

// ================ tf32 NT GEMM: C[M,Nc] = A[M,K] @ B[Nc,K]^T ================
// A, B in GEMM-ready permuted layout (tf32-rounded). CTA 128x128, 128 threads,
// 4 warps (2m x 2n), warp 64x64. 4-stage cp.async pipeline, K=16 per stage.
// EPI: 0 plain, 1 +bias, 2 +bias+GELU, 3 row-scale rs[m], 4 score mask+scale
// RND: round output to tf32. PERM: write output in permuted layout.
template <int EPI, int RND, int PERM>
__global__ void __launch_bounds__(128, 2) k_mma_gemm(
    const float* __restrict__ A, const float* __restrict__ B, float* __restrict__ C,
    int M, int Nc, int K,
    const float* __restrict__ bias, const float* __restrict__ rs,
    const int* __restrict__ mask)
{
    extern __shared__ uint32_t sm[];
    uint32_t* As = sm;                 // [4][128*16]
    uint32_t* Bs = sm + 4 * 2048;      // [4][128*16]

    const int tid = threadIdx.x;       // 0..127
    const int wid = tid >> 5;
    const int lane = tid & 31;
    const int wm = wid >> 1;
    const int wn = wid & 1;
    const int bx = blockIdx.x, by = blockIdx.y;

    const float* srcA = A + (size_t)(by * 128 + tid) * K;
    const float* srcB = B + (size_t)(bx * 128 + tid) * K;
    const uint32_t sa = smem_u32(As) + tid * 64;
    const uint32_t sb = smem_u32(Bs) + tid * 64;

    const int nch = K >> 4;            // >= 32 for all our shapes

    // prologue: stages 0..2
#pragma unroll
    for (int c = 0; c < 3; c++) {
        const float* pa = srcA + c * 16;
        const float* pb = srcB + c * 16;
        uint32_t da = sa + (uint32_t)c * 8192u;
        uint32_t db = sb + (uint32_t)c * 8192u;
#pragma unroll
        for (int q = 0; q < 4; q++) CP_ASYNC16(da + q * 16, pa + q * 4);
#pragma unroll
        for (int q = 0; q < 4; q++) CP_ASYNC16(db + q * 16, pb + q * 4);
        CP_COMMIT();
    }

    float acc[4][8][4];
#pragma unroll
    for (int i = 0; i < 4; i++)
#pragma unroll
        for (int j = 0; j < 8; j++)
#pragma unroll
            for (int q = 0; q < 4; q++) acc[i][j][q] = 0.0f;

    for (int c = 0; c < nch; ++c) {
        CP_WAIT2();
        __syncthreads();
        const int s = c & 3;
        const uint32_t* as = As + s * 2048;
        const uint32_t* bs = Bs + s * 2048;

        // B fragments: 8 n8-tiles
        uint4 fb[8];
#pragma unroll
        for (int nt = 0; nt < 8; nt++) {
            int nl = wn * 64 + nt * 8 + (lane >> 2);
            fb[nt] = *(const uint4*)&bs[nl * 16 + ((lane & 3) << 2)];
        }
        // mt loop: A fragments transient
#pragma unroll
        for (int mt = 0; mt < 4; mt++) {
            const int rl = wm * 64 + mt * 16 + (lane >> 2);
            uint4 fa0 = *(const uint4*)&as[rl * 16 + ((lane & 3) << 2)];
            uint4 fa1 = *(const uint4*)&as[(rl + 8) * 16 + ((lane & 3) << 2)];
#pragma unroll
            for (int nt = 0; nt < 8; nt++) {
                mma_tf32(acc[mt][nt], fa0.x, fa1.x, fa0.y, fa1.y, fb[nt].x, fb[nt].y);
                mma_tf32(acc[mt][nt], fa0.z, fa1.z, fa0.w, fa1.w, fb[nt].z, fb[nt].w);
            }
        }

        // issue stage c+3 (buffer (c+3)&3 == (c-1)&3, already drained)
        if (c + 3 < nch) {
            const int cn = c + 3;
            const float* pa = srcA + cn * 16;
            const float* pb = srcB + cn * 16;
            uint32_t da = sa + (uint32_t)(cn & 3) * 8192u;
            uint32_t db = sb + (uint32_t)(cn & 3) * 8192u;
#pragma unroll
            for (int q = 0; q < 4; q++) CP_ASYNC16(da + q * 16, pa + q * 4);
#pragma unroll
            for (int q = 0; q < 4; q++) CP_ASYNC16(db + q * 16, pb + q * 4);
        }
        CP_COMMIT();
    }

    // ---- epilogue ----
    const int col_b = bx * 128 + wn * 64 + (lane & 3) * 2;
#pragma unroll
    for (int mt = 0; mt < 4; mt++) {
#pragma unroll
        for (int h = 0; h < 2; h++) {
            int row = by * 128 + wm * 64 + mt * 16 + (lane >> 2) + h * 8;
            float rsv = (EPI == 3) ? rs[row] : 1.0f;
            float* Cr = C + (size_t)row * Nc;
            const int* Mr = (EPI == 4) ? (mask + (size_t)row * Nc) : nullptr;
#pragma unroll
            for (int nt = 0; nt < 8; nt++) {
                int col = col_b + nt * 8;   // even, col%16 <= 14
                float v0 = acc[mt][nt][h * 2 + 0];
                float v1 = acc[mt][nt][h * 2 + 1];
                if (EPI == 1 || EPI == 2) { v0 += bias[col]; v1 += bias[col + 1]; }
                if (EPI == 2) {
                    v0 = 0.5f * v0 * (1.0f + erff(v0 * 0.7071067811865475f));
                    v1 = 0.5f * v1 * (1.0f + erff(v1 * 0.7071067811865475f));
                }
                if (EPI == 3) { v0 *= rsv; v1 *= rsv; }
                if (EPI == 4) {
                    int2 mk = *(const int2*)(Mr + col);
                    v0 = mk.x ? NEGV : v0 * QKSCALE;
                    v1 = mk.y ? NEGV : v1 * QKSCALE;
                }
                if (RND) { v0 = rnd_tf32(v0); v1 = rnd_tf32(v1); }
                if (PERM) {
                    Cr[pi16(col)] = v0;
                    Cr[pi16(col + 1)] = v1;
                } else {
                    float2 o; o.x = v0; o.y = v1;
                    *(float2*)(Cr + col) = o;
                }
            }
        }
    }
}

// ====== transpose (rounded, permuted out): out[c][pi(r)] = tf32(in[r][c]) ===
__global__ void k_transpose(const float* __restrict__ in, float* __restrict__ out,
                            int R, int C) {
    __shared__ float t[32][33];
    int r0 = blockIdx.y * 32, c0 = blockIdx.x * 32;
    int x = threadIdx.x, y = threadIdx.y;
    for (int i = y; i < 32; i += 8)
        t[i][x] = in[(size_t)(r0 + i) * C + c0 + x];
    __syncthreads();
    for (int i = y; i < 32; i += 8)
        out[(size_t)(c0 + i) * R + pi16(r0 + x)] = rnd_tf32(t[x][i]);
}

// ========== transpose ALL 13 weights (rounded, permuted) in ONE launch ======
struct TPList {
    const float* src[13];
    float*       dst[13];
    int          R[13];
    int          C[13];
};
__global__ void k_transpose_all(TPList L) {
    int z = blockIdx.z;
    int R = L.R[z], C = L.C[z];
    int r0 = blockIdx.y * 32, c0 = blockIdx.x * 32;
    if (r0 >= R || c0 >= C) return;
    const float* in = L.src[z];
    float* out = L.dst[z];
    __shared__ float t[32][33];
    int x = threadIdx.x, y = threadIdx.y;
    for (int i = y; i < 32; i += 8)
        t[i][x] = in[(size_t)(r0 + i) * C + c0 + x];
    __syncthreads();
    for (int i = y; i < 32; i += 8)
        out[(size_t)(c0 + i) * R + pi16(r0 + x)] = rnd_tf32(t[x][i]);
}

// ===== drop_x build (normal + rounded-permuted) + x_init gather =============
__global__ void k_drop(const float* __restrict__ x, const int* __restrict__ idx,
                       float* __restrict__ dx, float* __restrict__ dxr,
                       float* __restrict__ out_init) {
    int r = blockIdx.x;
    const float* xr = x + (size_t)r * DD;
    float* dr  = dx  + (size_t)r * DD;
    float* drr = dxr + (size_t)r * DD;
    for (int c = threadIdx.x; c < DD; c += blockDim.x) {
        float v = xr[c];
        dr[c] = v;
        drr[pi16(c)] = rnd_tf32(v);
    }
    __syncthreads();
    for (int g = threadIdx.x; g < GG; g += blockDim.x) {
        int c = idx[r * GG + g];
        out_init[r * GG + g] = xr[c];
        dr[c] = 0.0f;
        drr[pi16(c)] = 0.0f;
    }
}

// ====== dual softmax combine (in-place; layout-invariant per row) ===========
__global__ void k_softmax(float* __restrict__ Sr, const float* __restrict__ Sf,
                          float* __restrict__ rinv) {
    int r = blockIdx.x, tid = threadIdx.x;
    float* sr = Sr + (size_t)r * NTOK;
    const float* sf = Sf + (size_t)r * NTOK;
    __shared__ float red[256];
    float m = -3.4e38f;
    for (int j = tid * 4; j < NTOK; j += 1024) {
        float4 a = *(const float4*)&sr[j];
        float4 b = *(const float4*)&sf[j];
        m = fmaxf(m, fmaxf(fmaxf(a.x, a.y), fmaxf(a.z, a.w)));
        m = fmaxf(m, fmaxf(fmaxf(b.x, b.y), fmaxf(b.z, b.w)));
    }
    red[tid] = m; __syncthreads();
    for (int s = 128; s > 0; s >>= 1) {
        if (tid < s) red[tid] = fmaxf(red[tid], red[tid + s]);
        __syncthreads();
    }
    m = red[0]; __syncthreads();
    float sum = 0.0f;
    for (int j = tid * 4; j < NTOK; j += 1024) {
        float4 a = *(const float4*)&sr[j];
        float4 b = *(const float4*)&sf[j];
        float4 p;
        p.x = expf(a.x - m) + GAM * expf(b.x - m);
        p.y = expf(a.y - m) + GAM * expf(b.y - m);
        p.z = expf(a.z - m) + GAM * expf(b.z - m);
        p.w = expf(a.w - m) + GAM * expf(b.w - m);
        sum += p.x + p.y + p.z + p.w;
        p.x = rnd_tf32(p.x); p.y = rnd_tf32(p.y);
        p.z = rnd_tf32(p.z); p.w = rnd_tf32(p.w);
        *(float4*)&sr[j] = p;
    }
    red[tid] = sum; __syncthreads();
    for (int s = 128; s > 0; s >>= 1) {
        if (tid < s) red[tid] += red[tid + s];
        __syncthreads();
    }
    if (tid == 0) rinv[r] = 1.0f / red[0];
}

// ===== residual add + LayerNorm (normal out + rounded-permuted out) =========
__global__ void k_addln(const float* __restrict__ a, const float* __restrict__ b,
                        const float* __restrict__ g, const float* __restrict__ bb,
                        float* __restrict__ out, float* __restrict__ outr) {
    int r = blockIdx.x, tid = threadIdx.x;
    __shared__ float s1[128], s2[128];
    const float* ar = a + (size_t)r * DD;
    const float* br = b + (size_t)r * DD;
    float4 va = *(const float4*)&ar[tid * 4];
    float4 vb = *(const float4*)&br[tid * 4];
    float v0 = va.x + vb.x, v1 = va.y + vb.y, v2 = va.z + vb.z, v3 = va.w + vb.w;
    s1[tid] = v0 + v1 + v2 + v3;
    s2[tid] = v0 * v0 + v1 * v1 + v2 * v2 + v3 * v3;
    __syncthreads();
    for (int s = 64; s > 0; s >>= 1) {
        if (tid < s) { s1[tid] += s1[tid + s]; s2[tid] += s2[tid + s]; }
        __syncthreads();
    }
    float mu = s1[0] * (1.0f / DD);
    float var = s2[0] * (1.0f / DD) - mu * mu;
    float rstd = rsqrtf(var + 1e-5f);
    int c = tid * 4;
    float4 o;
    o.x = (v0 - mu) * rstd * g[c + 0] + bb[c + 0];
    o.y = (v1 - mu) * rstd * g[c + 1] + bb[c + 1];
    o.z = (v2 - mu) * rstd * g[c + 2] + bb[c + 2];
    o.w = (v3 - mu) * rstd * g[c + 3] + bb[c + 3];
    *(float4*)&out[(size_t)r * DD + c] = o;
    float* orr = outr + (size_t)r * DD;
    orr[pi16(c + 0)] = rnd_tf32(o.x);
    orr[pi16(c + 1)] = rnd_tf32(o.y);
    orr[pi16(c + 2)] = rnd_tf32(o.z);
    orr[pi16(c + 3)] = rnd_tf32(o.w);
}

// ================= final gather =============================================
__global__ void k_gather(const float* __restrict__ H, const int* __restrict__ idx,
                         float* __restrict__ out) {
    int r = blockIdx.x;
    for (int g = threadIdx.x; g < GG; g += blockDim.x)
        out[r * GG + g] = H[(size_t)r * DD + idx[r * GG + g]];
}

// ================= host side ================================================
#define GEMM_SMEM (4 * 2048 * 2 * 4)   // 65536 bytes

template <int EPI, int RND, int PERM>
static void mma_gemm(const float* A, const float* B, float* C, int M, int Nc, int K,
                     const float* bias = nullptr, const float* rs = nullptr,
                     const int* mask = nullptr) {
    static bool configured = false;
    if (!configured) {
        cudaFuncSetAttribute(k_mma_gemm<EPI, RND, PERM>,
                             cudaFuncAttributeMaxDynamicSharedMemorySize, GEMM_SMEM);
        configured = true;
    }
    dim3 g(Nc / 128, M / 128);
    k_mma_gemm<EPI, RND, PERM><<<g, 128, GEMM_SMEM>>>(A, B, C, M, Nc, K, bias, rs, mask);
}

static void run_attention(const float* hr,
                          const float* Wqr_t, const float* Wkr_t,
                          const float* Wqf_t, const float* Wkf_t, const float* Wv_t,
                          const int* rmask, const int* fmask,
                          float* q, float* k, float* qf, float* kf, float* v, float* vt,
                          float* Sr, float* Sf, float* rinv, float* outbuf) {
    mma_gemm<0, 1, 1>(hr, Wqr_t, q,  NTOK, DD, DD);
    mma_gemm<0, 1, 1>(hr, Wkr_t, k,  NTOK, DD, DD);
    mma_gemm<0, 1, 1>(hr, Wqf_t, qf, NTOK, DD, DD);
    mma_gemm<0, 1, 1>(hr, Wkf_t, kf, NTOK, DD, DD);
    mma_gemm<0, 0, 0>(hr, Wv_t,  v,  NTOK, DD, DD);
    k_transpose<<<dim3(DD / 32, NTOK / 32), dim3(32, 8)>>>(v, vt, NTOK, DD);
    mma_gemm<4, 0, 1>(q,  k,  Sr, NTOK, NTOK, DD, nullptr, nullptr, rmask);
    mma_gemm<4, 0, 1>(qf, kf, Sf, NTOK, NTOK, DD, nullptr, nullptr, fmask);
    k_softmax<<<NTOK, 256>>>(Sr, Sf, rinv);
    mma_gemm<3, 0, 0>(Sr, vt, outbuf, NTOK, DD, NTOK, nullptr, rinv);
}

extern "C" void kernel_launch(void* const* d_in, const int* in_sizes, int n_in,
                              void* d_out, int out_size) {
    const float* x    = (const float*)d_in[0];
    const int*   idx  = (const int*)  d_in[1];
    const int*   rmsk = (const int*)  d_in[2];
    const int*   fmsk = (const int*)  d_in[3];
    const float* W[11] = {
        (const float*)d_in[4],  (const float*)d_in[5],  (const float*)d_in[6],
        (const float*)d_in[7],  (const float*)d_in[8],  (const float*)d_in[9],
        (const float*)d_in[10], (const float*)d_in[11], (const float*)d_in[12],
        (const float*)d_in[13], (const float*)d_in[24]  // head_W last
    };
    const float* fW1 = (const float*)d_in[14];
    const float* fb1 = (const float*)d_in[15];
    const float* fW2 = (const float*)d_in[16];
    const float* fb2 = (const float*)d_in[17];
    const float* l1g = (const float*)d_in[18];
    const float* l1b = (const float*)d_in[19];
    const float* l2g = (const float*)d_in[20];
    const float* l2b = (const float*)d_in[21];
    const float* l3g = (const float*)d_in[22];
    const float* l3b = (const float*)d_in[23];
    const float* hb  = (const float*)d_in[25];

    float* out       = (float*)d_out;
    float* out_init  = out;
    float* out_recon = out + (size_t)NTOK * GG;

    float *dropx, *dropxr, *q, *k, *qf, *kf, *v, *vt, *t0;
    float *h1, *h1r, *h2, *h2r, *ffb, *Sr, *Sf, *rinv, *wt;
    cudaGetSymbolAddress((void**)&dropx,  g_dropx);
    cudaGetSymbolAddress((void**)&dropxr, g_dropxr);
    cudaGetSymbolAddress((void**)&q,  g_q);
    cudaGetSymbolAddress((void**)&k,  g_k);
    cudaGetSymbolAddress((void**)&qf, g_qf);
    cudaGetSymbolAddress((void**)&kf, g_kf);
    cudaGetSymbolAddress((void**)&v,  g_v);
    cudaGetSymbolAddress((void**)&vt, g_vt);
    cudaGetSymbolAddress((void**)&t0, g_t0);
    cudaGetSymbolAddress((void**)&h1,  g_h1);
    cudaGetSymbolAddress((void**)&h1r, g_h1r);
    cudaGetSymbolAddress((void**)&h2,  g_h2);
    cudaGetSymbolAddress((void**)&h2r, g_h2r);
    cudaGetSymbolAddress((void**)&ffb, g_ffb);
    cudaGetSymbolAddress((void**)&Sr, g_Sr);
    cudaGetSymbolAddress((void**)&Sf, g_Sf);
    cudaGetSymbolAddress((void**)&rinv, g_rinv);
    cudaGetSymbolAddress((void**)&wt, g_wt);

    // transposed (rounded, permuted) weight destinations
    float* Wt[11];
    for (int i = 0; i < 11; i++) Wt[i] = wt + (size_t)i * DD * DD;
    float* fW1t = wt + (size_t)11 * DD * DD;            // [FFD, DD]
    float* fW2t = fW1t + (size_t)DD * FFD;              // [DD, FFD]

    // ---- launch 0: all 13 weight transposes in one kernel ----
    TPList L;
    for (int i = 0; i < 11; i++) {
        L.src[i] = W[i]; L.dst[i] = Wt[i]; L.R[i] = DD; L.C[i] = DD;
    }
    L.src[11] = fW1; L.dst[11] = fW1t; L.R[11] = DD;  L.C[11] = FFD;
    L.src[12] = fW2; L.dst[12] = fW2t; L.R[12] = FFD; L.C[12] = DD;
    k_transpose_all<<<dim3(64, 64, 13), dim3(32, 8)>>>(L);

    // ---- launch 1: drop_x (+rounded permuted) + x_init ----
    k_drop<<<NTOK, 128>>>(x, idx, dropx, dropxr, out_init);

    // encoder attention
    run_attention(dropxr, Wt[0], Wt[1], Wt[2], Wt[3], Wt[4], rmsk, fmsk,
                  q, k, qf, kf, v, vt, Sr, Sf, rinv, t0);
    k_addln<<<NTOK, 128>>>(t0, dropx, l1g, l1b, h1, h1r);

    // feed-forward
    mma_gemm<2, 1, 1>(h1r, fW1t, ffb, NTOK, FFD, DD, fb1);
    mma_gemm<1, 0, 0>(ffb, fW2t, t0, NTOK, DD, FFD, fb2);
    k_addln<<<NTOK, 128>>>(t0, h1, l2g, l2b, h2, h2r);

    // decoder attention
    run_attention(h2r, Wt[5], Wt[6], Wt[7], Wt[8], Wt[9], rmsk, fmsk,
                  q, k, qf, kf, v, vt, Sr, Sf, rinv, t0);
    k_addln<<<NTOK, 128>>>(t0, h2, l3g, l3b, h1, h1r);

    // head + x_recon gather
    mma_gemm<1, 0, 0>(h1r, Wt[10], t0, NTOK, DD, DD, hb);
    k_gather<<<NTOK, 128>>>(t0, idx, out_recon);
}